// round 14
// baseline (speedup 1.0000x reference)
#include <cuda_runtime.h>
#include <cuda_bf16.h>
#include <cuda_fp16.h>
#include <math.h>
#include <stdint.h>

// Problem constants
#define B_  2
#define S_  2048
#define E_  2048
#define H_  16
#define KV_ 4
#define G_  (H_ / KV_)   // 4
#define D_  128
#define NTOK (B_ * S_)   // 4096
#define NQKV 3072

// ---------------------------------------------------------------------------
// Scratch (device globals)
// ---------------------------------------------------------------------------
__device__ float g_cos[S_ * 64];
__device__ float g_sin[S_ * 64];

__device__ __half g_xh16[NTOK * E_];
__device__ __half g_xl16[NTOK * E_];
__device__ __half g_oh[NTOK * (H_ * D_)];
__device__ __half g_ol[NTOK * (H_ * D_)];
__device__ __half g_qb16h[NTOK * (H_ * D_)];
__device__ __half g_qb16l[NTOK * (H_ * D_)];
__device__ __half g_kb16[NTOK * (KV_ * D_)];
__device__ __half g_vt16[B_ * KV_ * D_ * S_];
__device__ __half g_Wqkvt16[NQKV * E_];
__device__ __half g_Wot16[E_ * E_];

// ---------------------------------------------------------------------------
// Tensor-core helpers (baseline ISA)
// ---------------------------------------------------------------------------
__device__ __forceinline__ uint32_t smem_u32(const void* p) {
    uint32_t a;
    asm("{ .reg .u64 t; cvta.to.shared.u64 t, %1; cvt.u32.u64 %0, t; }" : "=r"(a) : "l"(p));
    return a;
}

__device__ __forceinline__ void ldsm4(uint32_t* r, uint32_t addr) {
    asm volatile("ldmatrix.sync.aligned.m8n8.x4.shared.b16 {%0,%1,%2,%3}, [%4];"
                 : "=r"(r[0]), "=r"(r[1]), "=r"(r[2]), "=r"(r[3]) : "r"(addr));
}

__device__ __forceinline__ void mma16816h(float* d, const uint32_t* a, const uint32_t* b) {
    asm volatile(
        "mma.sync.aligned.m16n8k16.row.col.f32.f16.f16.f32 "
        "{%0,%1,%2,%3}, {%4,%5,%6,%7}, {%8,%9}, {%0,%1,%2,%3};"
        : "+f"(d[0]), "+f"(d[1]), "+f"(d[2]), "+f"(d[3])
        : "r"(a[0]), "r"(a[1]), "r"(a[2]), "r"(a[3]), "r"(b[0]), "r"(b[1]));
}

#define CP16(dst, src) \
    asm volatile("cp.async.cg.shared.global [%0], [%1], 16;" :: "r"(dst), "l"(src))
#define CP_COMMIT() asm volatile("cp.async.commit_group;" ::: "memory")
#define CP_WAIT0() asm volatile("cp.async.wait_group 0;" ::: "memory")
#define CP_WAIT1() asm volatile("cp.async.wait_group 1;" ::: "memory")

__device__ __forceinline__ uint32_t swz(int row, int chunk) {
    return (uint32_t)(row * 64 + ((chunk ^ ((row >> 1) & 3)) << 4));
}

__device__ __forceinline__ uint32_t pack_h16x2(float a, float b) {
    __half2 t = __floats2half2_rn(a, b);   // a -> low
    return *(uint32_t*)&t;
}

// ---------------------------------------------------------------------------
// fp16 2-term GEMM, 512 threads (16 warps: 4x4 grid, 32x32 warp tile).
// C = (Ah+Al) @ Bt^T, fp32 out.
// ---------------------------------------------------------------------------
#define BKC 32
#define TILE_B 8192
#define BUF16_B (3 * TILE_B)
#define FG16_SMEM (2 * BUF16_B)   // 48 KB

__global__ void __launch_bounds__(512, 1)
f16gemm_kernel(const __half* __restrict__ Ah, const __half* __restrict__ Al,
               const __half* __restrict__ Bh,
               float* __restrict__ C, int M, int N, int K) {
    extern __shared__ char smem[];
    const uint32_t smem_base = smem_u32(smem);
    const int t = threadIdx.x;
    const int lane = t & 31;
    const int wid = t >> 5;
    const int wm = wid & 3;          // 4 x 32 rows
    const int wn = wid >> 2;         // 4 x 32 cols
    const int bm = blockIdx.y * 128;
    const int bn = blockIdx.x * 128;

    const char* srcs[3] = {
        (const char*)(Ah + (size_t)bm * K),
        (const char*)(Al + (size_t)bm * K),
        (const char*)(Bh + (size_t)bn * K) };

    float acc[2][4][4];
#pragma unroll
    for (int i = 0; i < 2; i++)
#pragma unroll
        for (int j = 0; j < 4; j++)
#pragma unroll
            for (int u = 0; u < 4; u++) acc[i][j][u] = 0.f;

    const int NC = K / BKC;
    const size_t rowb = (size_t)K * 2;
    const int r_ = t >> 2, c_ = t & 3;     // 512 threads: 1 CP16 per tile

    {
#pragma unroll
        for (int tl = 0; tl < 3; tl++) {
            const char* src = srcs[tl];
            CP16(smem_base + tl * TILE_B + swz(r_, c_), src + (size_t)r_ * rowb + c_ * 16);
        }
        CP_COMMIT();
    }

    for (int ic = 0; ic < NC; ic++) {
        if (ic + 1 < NC) {
            const int k0b = (ic + 1) * BKC * 2;
            uint32_t sbase = smem_base + ((ic + 1) & 1) * BUF16_B;
#pragma unroll
            for (int tl = 0; tl < 3; tl++) {
                const char* src = srcs[tl] + k0b;
                CP16(sbase + tl * TILE_B + swz(r_, c_), src + (size_t)r_ * rowb + c_ * 16);
            }
            CP_COMMIT();
            CP_WAIT1();
        } else {
            CP_WAIT0();
        }
        __syncthreads();

        const uint32_t buf = smem_base + (ic & 1) * BUF16_B;
        const uint32_t a_h_base = buf;
        const uint32_t a_l_base = buf + TILE_B;
        const uint32_t b_base   = buf + 2 * TILE_B;

#pragma unroll
        for (int ks = 0; ks < 2; ks++) {
            uint32_t a_h[2][4], a_l[2][4];
#pragma unroll
            for (int mt = 0; mt < 2; mt++) {
                int row = wm * 32 + mt * 16 + (lane & 15);
                int chunk = ks * 2 + (lane >> 4);
                uint32_t off = swz(row, chunk);
                ldsm4(a_h[mt], a_h_base + off);
                ldsm4(a_l[mt], a_l_base + off);
            }
            uint32_t b_f[4][2];
#pragma unroll
            for (int np = 0; np < 2; np++) {
                int row = wn * 32 + np * 16 + ((lane >> 4) << 3) + (lane & 7);
                int chunk = ks * 2 + ((lane >> 3) & 1);
                uint32_t r4[4];
                ldsm4(r4, b_base + swz(row, chunk));
                b_f[np * 2][0] = r4[0]; b_f[np * 2][1] = r4[1];
                b_f[np * 2 + 1][0] = r4[2]; b_f[np * 2 + 1][1] = r4[3];
            }
#pragma unroll
            for (int mt = 0; mt < 2; mt++)
#pragma unroll
                for (int nt = 0; nt < 4; nt++)
                    mma16816h(acc[mt][nt], a_h[mt], b_f[nt]);
#pragma unroll
            for (int mt = 0; mt < 2; mt++)
#pragma unroll
                for (int nt = 0; nt < 4; nt++)
                    mma16816h(acc[mt][nt], a_l[mt], b_f[nt]);
        }
        __syncthreads();
    }

#pragma unroll
    for (int mt = 0; mt < 2; mt++) {
#pragma unroll
        for (int nt = 0; nt < 4; nt++) {
            int r0 = bm + wm * 32 + mt * 16 + (lane >> 2);
            int col = bn + wn * 32 + nt * 8 + ((lane & 3) << 1);
            float* p0 = C + (size_t)r0 * N + col;
            float* p1 = C + (size_t)(r0 + 8) * N + col;
            p0[0] = acc[mt][nt][0]; p0[1] = acc[mt][nt][1];
            p1[0] = acc[mt][nt][2]; p1[1] = acc[mt][nt][3];
        }
    }
}

// ---------------------------------------------------------------------------
// QKV GEMM (512 threads) with fused rope/split/transpose epilogue.
// ---------------------------------------------------------------------------
#define PS_STRIDE 129
#define QKV_SMEM (128 * PS_STRIDE * 4)   // 66,048 B

__global__ void __launch_bounds__(512, 1)
qkvgemm_kernel(const __half* __restrict__ Ah, const __half* __restrict__ Al,
               const __half* __restrict__ Bh,
               __half* __restrict__ qbh, __half* __restrict__ qbl,
               __half* __restrict__ kb, __half* __restrict__ vt) {
    extern __shared__ char smem[];
    const uint32_t smem_base = smem_u32(smem);
    const int t = threadIdx.x;
    const int lane = t & 31;
    const int wid = t >> 5;
    const int wm = wid & 3;
    const int wn = wid >> 2;
    const int bm = blockIdx.y * 128;
    const int bn = blockIdx.x * 128;
    const int K = E_;

    const char* srcs[3] = {
        (const char*)(Ah + (size_t)bm * K),
        (const char*)(Al + (size_t)bm * K),
        (const char*)(Bh + (size_t)bn * K) };

    float acc[2][4][4];
#pragma unroll
    for (int i = 0; i < 2; i++)
#pragma unroll
        for (int j = 0; j < 4; j++)
#pragma unroll
            for (int u = 0; u < 4; u++) acc[i][j][u] = 0.f;

    const int NC = K / BKC;
    const size_t rowb = (size_t)K * 2;
    const int r_ = t >> 2, c_ = t & 3;

    {
#pragma unroll
        for (int tl = 0; tl < 3; tl++) {
            const char* src = srcs[tl];
            CP16(smem_base + tl * TILE_B + swz(r_, c_), src + (size_t)r_ * rowb + c_ * 16);
        }
        CP_COMMIT();
    }

    for (int ic = 0; ic < NC; ic++) {
        if (ic + 1 < NC) {
            const int k0b = (ic + 1) * BKC * 2;
            uint32_t sbase = smem_base + ((ic + 1) & 1) * BUF16_B;
#pragma unroll
            for (int tl = 0; tl < 3; tl++) {
                const char* src = srcs[tl] + k0b;
                CP16(sbase + tl * TILE_B + swz(r_, c_), src + (size_t)r_ * rowb + c_ * 16);
            }
            CP_COMMIT();
            CP_WAIT1();
        } else {
            CP_WAIT0();
        }
        __syncthreads();

        const uint32_t buf = smem_base + (ic & 1) * BUF16_B;
        const uint32_t a_h_base = buf;
        const uint32_t a_l_base = buf + TILE_B;
        const uint32_t b_base   = buf + 2 * TILE_B;

#pragma unroll
        for (int ks = 0; ks < 2; ks++) {
            uint32_t a_h[2][4], a_l[2][4];
#pragma unroll
            for (int mt = 0; mt < 2; mt++) {
                int row = wm * 32 + mt * 16 + (lane & 15);
                int chunk = ks * 2 + (lane >> 4);
                uint32_t off = swz(row, chunk);
                ldsm4(a_h[mt], a_h_base + off);
                ldsm4(a_l[mt], a_l_base + off);
            }
            uint32_t b_f[4][2];
#pragma unroll
            for (int np = 0; np < 2; np++) {
                int row = wn * 32 + np * 16 + ((lane >> 4) << 3) + (lane & 7);
                int chunk = ks * 2 + ((lane >> 3) & 1);
                uint32_t r4[4];
                ldsm4(r4, b_base + swz(row, chunk));
                b_f[np * 2][0] = r4[0]; b_f[np * 2][1] = r4[1];
                b_f[np * 2 + 1][0] = r4[2]; b_f[np * 2 + 1][1] = r4[3];
            }
#pragma unroll
            for (int mt = 0; mt < 2; mt++)
#pragma unroll
                for (int nt = 0; nt < 4; nt++)
                    mma16816h(acc[mt][nt], a_h[mt], b_f[nt]);
#pragma unroll
            for (int mt = 0; mt < 2; mt++)
#pragma unroll
                for (int nt = 0; nt < 4; nt++)
                    mma16816h(acc[mt][nt], a_l[mt], b_f[nt]);
        }
        __syncthreads();
    }

    // ---- fused epilogue ----
    float* ps = (float*)smem;   // [128 rows][PS_STRIDE]
#pragma unroll
    for (int mt = 0; mt < 2; mt++) {
#pragma unroll
        for (int nt = 0; nt < 4; nt++) {
            int r0 = wm * 32 + mt * 16 + (lane >> 2);
            int col = wn * 32 + nt * 8 + ((lane & 3) << 1);
            ps[r0 * PS_STRIDE + col]       = acc[mt][nt][0];
            ps[r0 * PS_STRIDE + col + 1]   = acc[mt][nt][1];
            ps[(r0 + 8) * PS_STRIDE + col]     = acc[mt][nt][2];
            ps[(r0 + 8) * PS_STRIDE + col + 1] = acc[mt][nt][3];
        }
    }
    __syncthreads();

    if (bn < 2048) {
        const int h = bn >> 7;
        const float scale = 0.08838834764831845f;
        for (int idx = t; idx < 128 * 64; idx += 512) {
            int r = idx >> 6, i = idx & 63;
            int tok = bm + r;
            int s = tok & (S_ - 1);
            float c  = g_cos[s * 64 + i];
            float sn = g_sin[s * 64 + i];
            float v1 = ps[r * PS_STRIDE + i];
            float v2 = ps[r * PS_STRIDE + 64 + i];
            float r1 = (v1 * c - v2 * sn) * scale;
            float r2 = (v2 * c + v1 * sn) * scale;
            __half h1 = __float2half(r1);
            __half h2 = __float2half(r2);
            size_t dst = (size_t)tok * (H_ * D_) + h * 128;
            qbh[dst + i] = h1;
            qbl[dst + i] = __float2half(r1 - __half2float(h1));
            qbh[dst + 64 + i] = h2;
            qbl[dst + 64 + i] = __float2half(r2 - __half2float(h2));
        }
    } else if (bn < 2560) {
        const int kvh = (bn - 2048) >> 7;
        for (int idx = t; idx < 128 * 64; idx += 512) {
            int r = idx >> 6, i = idx & 63;
            int tok = bm + r;
            int s = tok & (S_ - 1);
            float c  = g_cos[s * 64 + i];
            float sn = g_sin[s * 64 + i];
            float v1 = ps[r * PS_STRIDE + i];
            float v2 = ps[r * PS_STRIDE + 64 + i];
            size_t dst = (size_t)tok * (KV_ * D_) + kvh * 128;
            kb[dst + i]      = __float2half(v1 * c - v2 * sn);
            kb[dst + 64 + i] = __float2half(v2 * c + v1 * sn);
        }
    } else {
        const int kvh = (bn - 2560) >> 7;
        const int b = bm >> 11;
        for (int idx = t; idx < 128 * 128; idx += 512) {
            int d = idx >> 7, rr = idx & 127;
            int tok = bm + rr;
            int s = tok & (S_ - 1);
            vt[(size_t)((b * KV_ + kvh) * 128 + d) * S_ + s] =
                __float2half(ps[rr * PS_STRIDE + d]);
        }
    }
}

// ---------------------------------------------------------------------------
// Conversions
// ---------------------------------------------------------------------------
__global__ void conv_split_f16_kernel(const float* __restrict__ A,
                                      __half* __restrict__ Ahi,
                                      __half* __restrict__ Alo, int total) {
    int i = blockIdx.x * blockDim.x + threadIdx.x;
    if (i >= total) return;
    float v = A[i];
    __half h = __float2half(v);
    Ahi[i] = h;
    Alo[i] = __float2half(v - __half2float(h));
}

__global__ void conv_transpose_all_kernel(const float* __restrict__ Wq,
                                          const float* __restrict__ Wk,
                                          const float* __restrict__ Wv,
                                          const float* __restrict__ Wo,
                                          __half* __restrict__ Wqkvt,
                                          __half* __restrict__ Wot) {
    __shared__ float tile[32][33];
    const int z = blockIdx.z;
    const float* W;
    __half* T;
    int N;
    if (z == 0)      { W = Wq; T = Wqkvt;                       N = 2048; }
    else if (z == 1) { W = Wk; T = Wqkvt + (size_t)2048 * E_;   N = 512; }
    else if (z == 2) { W = Wv; T = Wqkvt + (size_t)2560 * E_;   N = 512; }
    else             { W = Wo; T = Wot;                         N = 2048; }
    int n0 = blockIdx.x * 32;
    if (n0 >= N) return;
    int k0 = blockIdx.y * 32;
    int tx = threadIdx.x & 31, ty = threadIdx.x >> 5;
#pragma unroll
    for (int i = 0; i < 32; i += 8)
        tile[ty + i][tx] = W[(size_t)(k0 + ty + i) * N + n0 + tx];
    __syncthreads();
#pragma unroll
    for (int i = 0; i < 32; i += 8)
        T[(size_t)(n0 + ty + i) * E_ + k0 + tx] = __float2half(tile[tx][ty + i]);
}

// ---------------------------------------------------------------------------
// RoPE tables
// ---------------------------------------------------------------------------
__global__ void build_tables_kernel() {
    int idx = blockIdx.x * blockDim.x + threadIdx.x;
    if (idx >= S_ * 64) return;
    int i = idx & 63;
    int s = idx >> 6;
    double inv = pow(10000.0, -(double)i / 64.0);
    double ang = (double)s * inv;
    g_cos[idx] = (float)cos(ang);
    g_sin[idx] = (float)sin(ang);
}

// ---------------------------------------------------------------------------
// Flash attention, all-fp16 operands (validated R11-R13, unchanged)
// ---------------------------------------------------------------------------
#define ATT_SMEM 131072
#define KV_BUF(buf) (65536 + (buf) * 32768)

__global__ void __launch_bounds__(256, 1)
attn3_kernel(const __half* __restrict__ qbh, const __half* __restrict__ qbl,
             const __half* __restrict__ kb, const __half* __restrict__ vt,
             __half* __restrict__ oh, __half* __restrict__ ol) {
    extern __shared__ char smem[];
    const uint32_t sb = smem_u32(smem);
    const int qt = (int)gridDim.x - 1 - (int)blockIdx.x;
    const int h = blockIdx.y, b = blockIdx.z;
    const int kvh = h >> 2;
    const int t = threadIdx.x, lane = t & 31, w = t >> 5;
    const int q0 = qt * 128;
    const int kt_end = q0 + 128;

    auto load_kv = [&](int kt, int buf) {
        const uint32_t kvb = sb + KV_BUF(buf);
#pragma unroll
        for (int j = 0; j < 4; j++) {
            int idx = t + j * 256;
            int dc = idx >> 8, rem = idx & 255;
            int r = rem >> 2, c = rem & 3;
            const __half* src =
                kb + (size_t)(b * S_ + kt + r) * (KV_ * D_) + kvh * 128 + dc * 32 + c * 8;
            CP16(kvb + dc * 4096 + swz(r, c), src);
        }
#pragma unroll
        for (int j = 0; j < 4; j++) {
            int idx = t + j * 256;
            int kc = idx >> 9, rem = idx & 511;
            int r = rem >> 2, c = rem & 3;
            const __half* src =
                vt + (size_t)((b * KV_ + kvh) * 128 + r) * S_ + kt + kc * 32 + c * 8;
            CP16(kvb + 16384 + kc * 8192 + swz(r, c), src);
        }
    };

    {
        const __half* srcs[2] = { qbh, qbl };
#pragma unroll
        for (int j = 0; j < 16; j++) {
            int idx = t + j * 256;
            int prec = idx >> 11, rem = idx & 2047;
            int dc = rem >> 9, rem2 = rem & 511;
            int r = rem2 >> 2, c = rem2 & 3;
            const __half* src =
                srcs[prec] + (size_t)(b * S_ + q0 + r) * (H_ * D_) + h * 128 + dc * 32 + c * 8;
            CP16(sb + (prec * 4 + dc) * 8192 + swz(r, c), src);
        }
        load_kv(0, 0);
        CP_COMMIT();
    }

    float o_acc[16][4];
#pragma unroll
    for (int i = 0; i < 16; i++)
#pragma unroll
        for (int u = 0; u < 4; u++) o_acc[i][u] = 0.f;
    float m0 = -INFINITY, m1 = -INFINITY, l0 = 0.f, l1 = 0.f;

    for (int kt = 0; kt < kt_end; kt += 64) {
        const int ti = kt >> 6;
        if (kt + 64 < kt_end) load_kv(kt + 64, (ti + 1) & 1);
        CP_COMMIT();
        CP_WAIT1();
        __syncthreads();

        const uint32_t kvb = sb + KV_BUF(ti & 1);

        float sf[8][4];
#pragma unroll
        for (int nt = 0; nt < 8; nt++)
#pragma unroll
            for (int u = 0; u < 4; u++) sf[nt][u] = 0.f;

#pragma unroll
        for (int j = 0; j < 8; j++) {
            int dc = j >> 1, ks = j & 1;
            uint32_t ah[4], al[4];
            uint32_t aoff = swz(w * 16 + (lane & 15), ks * 2 + (lane >> 4));
            ldsm4(ah, sb + (0 * 4 + dc) * 8192 + aoff);
            ldsm4(al, sb + (1 * 4 + dc) * 8192 + aoff);
            uint32_t bf[8][2];
#pragma unroll
            for (int np = 0; np < 4; np++) {
                uint32_t boff = swz(np * 16 + ((lane >> 4) << 3) + (lane & 7),
                                    ks * 2 + ((lane >> 3) & 1));
                uint32_t r4[4];
                ldsm4(r4, kvb + dc * 4096 + boff);
                bf[np * 2][0] = r4[0]; bf[np * 2][1] = r4[1];
                bf[np * 2 + 1][0] = r4[2]; bf[np * 2 + 1][1] = r4[3];
            }
#pragma unroll
            for (int nt = 0; nt < 8; nt++)
                mma16816h(sf[nt], ah, bf[nt]);
#pragma unroll
            for (int nt = 0; nt < 8; nt++)
                mma16816h(sf[nt], al, bf[nt]);
        }

        if (kt + 63 > q0 + w * 16) {
            int row0g = q0 + w * 16 + (lane >> 2);
            int colb = kt + ((lane & 3) << 1);
#pragma unroll
            for (int nt = 0; nt < 8; nt++) {
                int c0 = colb + nt * 8;
                if (c0 > row0g)     sf[nt][0] = -INFINITY;
                if (c0 + 1 > row0g) sf[nt][1] = -INFINITY;
                if (c0 > row0g + 8)     sf[nt][2] = -INFINITY;
                if (c0 + 1 > row0g + 8) sf[nt][3] = -INFINITY;
            }
        }

        float mx0 = -INFINITY, mx1 = -INFINITY;
#pragma unroll
        for (int nt = 0; nt < 8; nt++) {
            mx0 = fmaxf(mx0, fmaxf(sf[nt][0], sf[nt][1]));
            mx1 = fmaxf(mx1, fmaxf(sf[nt][2], sf[nt][3]));
        }
        mx0 = fmaxf(mx0, __shfl_xor_sync(0xffffffffu, mx0, 1));
        mx0 = fmaxf(mx0, __shfl_xor_sync(0xffffffffu, mx0, 2));
        mx1 = fmaxf(mx1, __shfl_xor_sync(0xffffffffu, mx1, 1));
        mx1 = fmaxf(mx1, __shfl_xor_sync(0xffffffffu, mx1, 2));
        float mn0 = fmaxf(m0, mx0), mn1 = fmaxf(m1, mx1);
        float corr0 = __expf(m0 - mn0), corr1 = __expf(m1 - mn1);
        float sum0 = 0.f, sum1 = 0.f;
#pragma unroll
        for (int nt = 0; nt < 8; nt++) {
            float p0 = __expf(sf[nt][0] - mn0); sf[nt][0] = p0; sum0 += p0;
            float p1 = __expf(sf[nt][1] - mn0); sf[nt][1] = p1; sum0 += p1;
            float p2 = __expf(sf[nt][2] - mn1); sf[nt][2] = p2; sum1 += p2;
            float p3 = __expf(sf[nt][3] - mn1); sf[nt][3] = p3; sum1 += p3;
        }
        sum0 += __shfl_xor_sync(0xffffffffu, sum0, 1);
        sum0 += __shfl_xor_sync(0xffffffffu, sum0, 2);
        sum1 += __shfl_xor_sync(0xffffffffu, sum1, 1);
        sum1 += __shfl_xor_sync(0xffffffffu, sum1, 2);
        l0 = l0 * corr0 + sum0;
        l1 = l1 * corr1 + sum1;
        m0 = mn0; m1 = mn1;
#pragma unroll
        for (int i = 0; i < 16; i++) {
            o_acc[i][0] *= corr0; o_acc[i][1] *= corr0;
            o_acc[i][2] *= corr1; o_acc[i][3] *= corr1;
        }

#pragma unroll
        for (int s4 = 0; s4 < 4; s4++) {
            uint32_t ah[4], al[4];
#pragma unroll
            for (int half = 0; half < 2; half++) {
                const float* pp = sf[2 * s4 + half];
                float h0f = __half2float(__float2half(pp[0]));
                float h1f = __half2float(__float2half(pp[1]));
                float h2f = __half2float(__float2half(pp[2]));
                float h3f = __half2float(__float2half(pp[3]));
                ah[half * 2 + 0] = pack_h16x2(h0f, h1f);
                ah[half * 2 + 1] = pack_h16x2(h2f, h3f);
                al[half * 2 + 0] = pack_h16x2(pp[0] - h0f, pp[1] - h1f);
                al[half * 2 + 1] = pack_h16x2(pp[2] - h2f, pp[3] - h3f);
            }
            int kc = s4 >> 1;
            uint32_t chunk = (uint32_t)((s4 & 1) * 2 + ((lane >> 3) & 1));
            uint32_t vb[8][4];
#pragma unroll
            for (int np = 0; np < 8; np++) {
                uint32_t boff = swz(np * 16 + ((lane >> 4) << 3) + (lane & 7), chunk);
                ldsm4(vb[np], kvb + 16384 + kc * 8192 + boff);
            }
#pragma unroll
            for (int np = 0; np < 8; np++) {
                mma16816h(o_acc[np * 2], ah, vb[np]);
                mma16816h(o_acc[np * 2 + 1], ah, vb[np] + 2);
            }
#pragma unroll
            for (int np = 0; np < 8; np++) {
                mma16816h(o_acc[np * 2], al, vb[np]);
                mma16816h(o_acc[np * 2 + 1], al, vb[np] + 2);
            }
        }
        __syncthreads();
    }

    float inv0 = 1.f / l0, inv1 = 1.f / l1;
    int row0g = q0 + w * 16 + (lane >> 2);
    size_t base0 = (size_t)(b * S_ + row0g) * (H_ * D_) + h * 128 + ((lane & 3) << 1);
    size_t base1 = base0 + 8 * (size_t)(H_ * D_);
#pragma unroll
    for (int nt = 0; nt < 16; nt++) {
        float v0 = o_acc[nt][0] * inv0, v1 = o_acc[nt][1] * inv0;
        float v2 = o_acc[nt][2] * inv1, v3 = o_acc[nt][3] * inv1;
        float h0f = __half2float(__float2half(v0));
        float h1f = __half2float(__float2half(v1));
        float h2f = __half2float(__float2half(v2));
        float h3f = __half2float(__float2half(v3));
        *(uint32_t*)(oh + base0 + nt * 8) = pack_h16x2(h0f, h1f);
        *(uint32_t*)(ol + base0 + nt * 8) = pack_h16x2(v0 - h0f, v1 - h1f);
        *(uint32_t*)(oh + base1 + nt * 8) = pack_h16x2(h2f, h3f);
        *(uint32_t*)(ol + base1 + nt * 8) = pack_h16x2(v2 - h2f, v3 - h3f);
    }
}

// ---------------------------------------------------------------------------
// Launch
// ---------------------------------------------------------------------------
extern "C" void kernel_launch(void* const* d_in, const int* in_sizes, int n_in,
                              void* d_out, int out_size) {
    const float *x, *Wq, *Wk, *Wv, *Wo;
    if (in_sizes[0] == NTOK * E_) {
        x  = (const float*)d_in[0];
        Wq = (const float*)d_in[1];
        Wk = (const float*)d_in[2];
        Wv = (const float*)d_in[3];
        Wo = (const float*)d_in[4];
    } else {
        Wk = (const float*)d_in[0];
        Wo = (const float*)d_in[1];
        Wq = (const float*)d_in[2];
        Wv = (const float*)d_in[3];
        x  = (const float*)d_in[4];
    }
    float* out = (float*)d_out;

    __half *xh, *xl, *oh, *ol, *qbh, *qbl, *kb, *vt, *Wqkvt16, *Wot16;
    cudaGetSymbolAddress((void**)&xh, g_xh16);
    cudaGetSymbolAddress((void**)&xl, g_xl16);
    cudaGetSymbolAddress((void**)&oh, g_oh);
    cudaGetSymbolAddress((void**)&ol, g_ol);
    cudaGetSymbolAddress((void**)&qbh, g_qb16h);
    cudaGetSymbolAddress((void**)&qbl, g_qb16l);
    cudaGetSymbolAddress((void**)&kb, g_kb16);
    cudaGetSymbolAddress((void**)&vt, g_vt16);
    cudaGetSymbolAddress((void**)&Wqkvt16, g_Wqkvt16);
    cudaGetSymbolAddress((void**)&Wot16, g_Wot16);

    cudaFuncSetAttribute(f16gemm_kernel, cudaFuncAttributeMaxDynamicSharedMemorySize, FG16_SMEM);
    cudaFuncSetAttribute(qkvgemm_kernel, cudaFuncAttributeMaxDynamicSharedMemorySize, QKV_SMEM);
    cudaFuncSetAttribute(attn3_kernel, cudaFuncAttributeMaxDynamicSharedMemorySize, ATT_SMEM);

    build_tables_kernel<<<(S_ * 64 + 255) / 256, 256>>>();
    conv_split_f16_kernel<<<(NTOK * E_ + 255) / 256, 256>>>(x, xh, xl, NTOK * E_);
    {
        dim3 g(E_ / 32, E_ / 32, 4);
        conv_transpose_all_kernel<<<g, 256>>>(Wq, Wk, Wv, Wo, Wqkvt16, Wot16);
    }
    {
        dim3 g(NQKV / 128, NTOK / 128);
        qkvgemm_kernel<<<g, 512, QKV_SMEM>>>(xh, xl, Wqkvt16, qbh, qbl, kb, vt);
    }
    {
        dim3 ga(S_ / 128, H_, B_);
        attn3_kernel<<<ga, 256, ATT_SMEM>>>(qbh, qbl, kb, vt, oh, ol);
    }
    {
        dim3 go(E_ / 128, NTOK / 128);
        f16gemm_kernel<<<go, 512, FG16_SMEM>>>(oh, ol, Wot16, out, NTOK, E_, E_);
    }
}

// round 15
// speedup vs baseline: 1.3100x; 1.3100x over previous
#include <cuda_runtime.h>
#include <cuda_bf16.h>
#include <cuda_fp16.h>
#include <math.h>
#include <stdint.h>

// Problem constants
#define B_  2
#define S_  2048
#define E_  2048
#define H_  16
#define KV_ 4
#define G_  (H_ / KV_)   // 4
#define D_  128
#define NTOK (B_ * S_)   // 4096
#define NQKV 3072

// ---------------------------------------------------------------------------
// Scratch (device globals)
// ---------------------------------------------------------------------------
__device__ float g_cos[S_ * 64];
__device__ float g_sin[S_ * 64];

__device__ __half g_x16[NTOK * E_];             // x single fp16
__device__ __half g_o16[NTOK * (H_ * D_)];      // attn out single fp16
__device__ __half g_qb16h[NTOK * (H_ * D_)];    // Q post-rope hi
__device__ __half g_qb16l[NTOK * (H_ * D_)];    // Q post-rope lo
__device__ __half g_kb16[NTOK * (KV_ * D_)];    // K post-rope single
__device__ __half g_vt16[B_ * KV_ * D_ * S_];   // V transposed single
__device__ __half g_Wqkvt16[NQKV * E_];
__device__ __half g_Wot16[E_ * E_];

// ---------------------------------------------------------------------------
// Tensor-core helpers (baseline ISA)
// ---------------------------------------------------------------------------
__device__ __forceinline__ uint32_t smem_u32(const void* p) {
    uint32_t a;
    asm("{ .reg .u64 t; cvta.to.shared.u64 t, %1; cvt.u32.u64 %0, t; }" : "=r"(a) : "l"(p));
    return a;
}

__device__ __forceinline__ void ldsm4(uint32_t* r, uint32_t addr) {
    asm volatile("ldmatrix.sync.aligned.m8n8.x4.shared.b16 {%0,%1,%2,%3}, [%4];"
                 : "=r"(r[0]), "=r"(r[1]), "=r"(r[2]), "=r"(r[3]) : "r"(addr));
}

__device__ __forceinline__ void mma16816h(float* d, const uint32_t* a, const uint32_t* b) {
    asm volatile(
        "mma.sync.aligned.m16n8k16.row.col.f32.f16.f16.f32 "
        "{%0,%1,%2,%3}, {%4,%5,%6,%7}, {%8,%9}, {%0,%1,%2,%3};"
        : "+f"(d[0]), "+f"(d[1]), "+f"(d[2]), "+f"(d[3])
        : "r"(a[0]), "r"(a[1]), "r"(a[2]), "r"(a[3]), "r"(b[0]), "r"(b[1]));
}

#define CP16(dst, src) \
    asm volatile("cp.async.cg.shared.global [%0], [%1], 16;" :: "r"(dst), "l"(src))
#define CP_COMMIT() asm volatile("cp.async.commit_group;" ::: "memory")
#define CP_WAIT0() asm volatile("cp.async.wait_group 0;" ::: "memory")
#define CP_WAIT1() asm volatile("cp.async.wait_group 1;" ::: "memory")

__device__ __forceinline__ uint32_t swz(int row, int chunk) {
    return (uint32_t)(row * 64 + ((chunk ^ ((row >> 1) & 3)) << 4));
}

__device__ __forceinline__ uint32_t pack_h16x2(float a, float b) {
    __half2 t = __floats2half2_rn(a, b);   // a -> low
    return *(uint32_t*)&t;
}

// ---------------------------------------------------------------------------
// Single-fp16 GEMM mainloop macro pieces (256 threads, 2x4 warp grid, 64x32
// warp tile, BK=32, double-buffered cp.async). A and B single precision.
// ---------------------------------------------------------------------------
#define BKC 32
#define TILE_B 8192
#define BUF1_B (2 * TILE_B)         // A + B tiles = 16 KB/stage
#define FG_SMEM (2 * BUF1_B)        // 32 KB

// Wo projection: C[M,N] fp32 = A @ Bt^T
__global__ void __launch_bounds__(256, 1)
f16gemm_kernel(const __half* __restrict__ A, const __half* __restrict__ Bh,
               float* __restrict__ C, int M, int N, int K) {
    extern __shared__ char smem[];
    const uint32_t smem_base = smem_u32(smem);
    const int t = threadIdx.x;
    const int lane = t & 31;
    const int wid = t >> 5;
    const int wm = wid & 1;
    const int wn = wid >> 1;
    const int bm = blockIdx.y * 128;
    const int bn = blockIdx.x * 128;

    const char* srcs[2] = {
        (const char*)(A + (size_t)bm * K),
        (const char*)(Bh + (size_t)bn * K) };

    float acc[4][4][4];
#pragma unroll
    for (int i = 0; i < 4; i++)
#pragma unroll
        for (int j = 0; j < 4; j++)
#pragma unroll
            for (int u = 0; u < 4; u++) acc[i][j][u] = 0.f;

    const int NC = K / BKC;
    const size_t rowb = (size_t)K * 2;

    {
#pragma unroll
        for (int tl = 0; tl < 2; tl++) {
            const char* src = srcs[tl];
            uint32_t dstt = smem_base + tl * TILE_B;
#pragma unroll
            for (int j = 0; j < 2; j++) {
                int idx = t + j * 256;
                int r = idx >> 2, c = idx & 3;
                CP16(dstt + swz(r, c), src + (size_t)r * rowb + c * 16);
            }
        }
        CP_COMMIT();
    }

    for (int ic = 0; ic < NC; ic++) {
        if (ic + 1 < NC) {
            const int k0b = (ic + 1) * BKC * 2;
            uint32_t sbase = smem_base + ((ic + 1) & 1) * BUF1_B;
#pragma unroll
            for (int tl = 0; tl < 2; tl++) {
                const char* src = srcs[tl] + k0b;
                uint32_t dstt = sbase + tl * TILE_B;
#pragma unroll
                for (int j = 0; j < 2; j++) {
                    int idx = t + j * 256;
                    int r = idx >> 2, c = idx & 3;
                    CP16(dstt + swz(r, c), src + (size_t)r * rowb + c * 16);
                }
            }
            CP_COMMIT();
            CP_WAIT1();
        } else {
            CP_WAIT0();
        }
        __syncthreads();

        const uint32_t buf = smem_base + (ic & 1) * BUF1_B;
        const uint32_t a_base = buf;
        const uint32_t b_base = buf + TILE_B;

#pragma unroll
        for (int ks = 0; ks < 2; ks++) {
            uint32_t a_f[4][4];
#pragma unroll
            for (int mt = 0; mt < 4; mt++) {
                int row = wm * 64 + mt * 16 + (lane & 15);
                int chunk = ks * 2 + (lane >> 4);
                ldsm4(a_f[mt], a_base + swz(row, chunk));
            }
            uint32_t b_f[4][2];
#pragma unroll
            for (int np = 0; np < 2; np++) {
                int row = wn * 32 + np * 16 + ((lane >> 4) << 3) + (lane & 7);
                int chunk = ks * 2 + ((lane >> 3) & 1);
                uint32_t r4[4];
                ldsm4(r4, b_base + swz(row, chunk));
                b_f[np * 2][0] = r4[0]; b_f[np * 2][1] = r4[1];
                b_f[np * 2 + 1][0] = r4[2]; b_f[np * 2 + 1][1] = r4[3];
            }
#pragma unroll
            for (int mt = 0; mt < 4; mt++)
#pragma unroll
                for (int nt = 0; nt < 4; nt++)
                    mma16816h(acc[mt][nt], a_f[mt], b_f[nt]);
        }
        __syncthreads();
    }

#pragma unroll
    for (int mt = 0; mt < 4; mt++) {
#pragma unroll
        for (int nt = 0; nt < 4; nt++) {
            int r0 = bm + wm * 64 + mt * 16 + (lane >> 2);
            int col = bn + wn * 32 + nt * 8 + ((lane & 3) << 1);
            float* p0 = C + (size_t)r0 * N + col;
            float* p1 = C + (size_t)(r0 + 8) * N + col;
            p0[0] = acc[mt][nt][0]; p0[1] = acc[mt][nt][1];
            p1[0] = acc[mt][nt][2]; p1[1] = acc[mt][nt][3];
        }
    }
}

// ---------------------------------------------------------------------------
// QKV GEMM (single-fp16 A, fused rope/split/transpose epilogue)
// ---------------------------------------------------------------------------
#define PS_STRIDE 129
#define QKV_SMEM (128 * PS_STRIDE * 4)   // 66,048 B

__global__ void __launch_bounds__(256, 1)
qkvgemm_kernel(const __half* __restrict__ A, const __half* __restrict__ Bh,
               __half* __restrict__ qbh, __half* __restrict__ qbl,
               __half* __restrict__ kb, __half* __restrict__ vt) {
    extern __shared__ char smem[];
    const uint32_t smem_base = smem_u32(smem);
    const int t = threadIdx.x;
    const int lane = t & 31;
    const int wid = t >> 5;
    const int wm = wid & 1;
    const int wn = wid >> 1;
    const int bm = blockIdx.y * 128;
    const int bn = blockIdx.x * 128;
    const int K = E_;

    const char* srcs[2] = {
        (const char*)(A + (size_t)bm * K),
        (const char*)(Bh + (size_t)bn * K) };

    float acc[4][4][4];
#pragma unroll
    for (int i = 0; i < 4; i++)
#pragma unroll
        for (int j = 0; j < 4; j++)
#pragma unroll
            for (int u = 0; u < 4; u++) acc[i][j][u] = 0.f;

    const int NC = K / BKC;
    const size_t rowb = (size_t)K * 2;

    {
#pragma unroll
        for (int tl = 0; tl < 2; tl++) {
            const char* src = srcs[tl];
            uint32_t dstt = smem_base + tl * TILE_B;
#pragma unroll
            for (int j = 0; j < 2; j++) {
                int idx = t + j * 256;
                int r = idx >> 2, c = idx & 3;
                CP16(dstt + swz(r, c), src + (size_t)r * rowb + c * 16);
            }
        }
        CP_COMMIT();
    }

    for (int ic = 0; ic < NC; ic++) {
        if (ic + 1 < NC) {
            const int k0b = (ic + 1) * BKC * 2;
            uint32_t sbase = smem_base + ((ic + 1) & 1) * BUF1_B;
#pragma unroll
            for (int tl = 0; tl < 2; tl++) {
                const char* src = srcs[tl] + k0b;
                uint32_t dstt = sbase + tl * TILE_B;
#pragma unroll
                for (int j = 0; j < 2; j++) {
                    int idx = t + j * 256;
                    int r = idx >> 2, c = idx & 3;
                    CP16(dstt + swz(r, c), src + (size_t)r * rowb + c * 16);
                }
            }
            CP_COMMIT();
            CP_WAIT1();
        } else {
            CP_WAIT0();
        }
        __syncthreads();

        const uint32_t buf = smem_base + (ic & 1) * BUF1_B;
        const uint32_t a_base = buf;
        const uint32_t b_base = buf + TILE_B;

#pragma unroll
        for (int ks = 0; ks < 2; ks++) {
            uint32_t a_f[4][4];
#pragma unroll
            for (int mt = 0; mt < 4; mt++) {
                int row = wm * 64 + mt * 16 + (lane & 15);
                int chunk = ks * 2 + (lane >> 4);
                ldsm4(a_f[mt], a_base + swz(row, chunk));
            }
            uint32_t b_f[4][2];
#pragma unroll
            for (int np = 0; np < 2; np++) {
                int row = wn * 32 + np * 16 + ((lane >> 4) << 3) + (lane & 7);
                int chunk = ks * 2 + ((lane >> 3) & 1);
                uint32_t r4[4];
                ldsm4(r4, b_base + swz(row, chunk));
                b_f[np * 2][0] = r4[0]; b_f[np * 2][1] = r4[1];
                b_f[np * 2 + 1][0] = r4[2]; b_f[np * 2 + 1][1] = r4[3];
            }
#pragma unroll
            for (int mt = 0; mt < 4; mt++)
#pragma unroll
                for (int nt = 0; nt < 4; nt++)
                    mma16816h(acc[mt][nt], a_f[mt], b_f[nt]);
        }
        __syncthreads();
    }

    // ---- fused epilogue ----
    float* ps = (float*)smem;   // [128 rows][PS_STRIDE]
#pragma unroll
    for (int mt = 0; mt < 4; mt++) {
#pragma unroll
        for (int nt = 0; nt < 4; nt++) {
            int r0 = wm * 64 + mt * 16 + (lane >> 2);
            int col = wn * 32 + nt * 8 + ((lane & 3) << 1);
            ps[r0 * PS_STRIDE + col]       = acc[mt][nt][0];
            ps[r0 * PS_STRIDE + col + 1]   = acc[mt][nt][1];
            ps[(r0 + 8) * PS_STRIDE + col]     = acc[mt][nt][2];
            ps[(r0 + 8) * PS_STRIDE + col + 1] = acc[mt][nt][3];
        }
    }
    __syncthreads();

    if (bn < 2048) {
        const int h = bn >> 7;
        const float scale = 0.08838834764831845f;
        for (int idx = t; idx < 128 * 64; idx += 256) {
            int r = idx >> 6, i = idx & 63;
            int tok = bm + r;
            int s = tok & (S_ - 1);
            float c  = g_cos[s * 64 + i];
            float sn = g_sin[s * 64 + i];
            float v1 = ps[r * PS_STRIDE + i];
            float v2 = ps[r * PS_STRIDE + 64 + i];
            float r1 = (v1 * c - v2 * sn) * scale;
            float r2 = (v2 * c + v1 * sn) * scale;
            __half h1 = __float2half(r1);
            __half h2 = __float2half(r2);
            size_t dst = (size_t)tok * (H_ * D_) + h * 128;
            qbh[dst + i] = h1;
            qbl[dst + i] = __float2half(r1 - __half2float(h1));
            qbh[dst + 64 + i] = h2;
            qbl[dst + 64 + i] = __float2half(r2 - __half2float(h2));
        }
    } else if (bn < 2560) {
        const int kvh = (bn - 2048) >> 7;
        for (int idx = t; idx < 128 * 64; idx += 256) {
            int r = idx >> 6, i = idx & 63;
            int tok = bm + r;
            int s = tok & (S_ - 1);
            float c  = g_cos[s * 64 + i];
            float sn = g_sin[s * 64 + i];
            float v1 = ps[r * PS_STRIDE + i];
            float v2 = ps[r * PS_STRIDE + 64 + i];
            size_t dst = (size_t)tok * (KV_ * D_) + kvh * 128;
            kb[dst + i]      = __float2half(v1 * c - v2 * sn);
            kb[dst + 64 + i] = __float2half(v2 * c + v1 * sn);
        }
    } else {
        const int kvh = (bn - 2560) >> 7;
        const int b = bm >> 11;
        for (int idx = t; idx < 128 * 128; idx += 256) {
            int d = idx >> 7, rr = idx & 127;
            int tok = bm + rr;
            int s = tok & (S_ - 1);
            vt[(size_t)((b * KV_ + kvh) * 128 + d) * S_ + s] =
                __float2half(ps[rr * PS_STRIDE + d]);
        }
    }
}

// ---------------------------------------------------------------------------
// Conversions
// ---------------------------------------------------------------------------
__global__ void conv_f16_kernel(const float* __restrict__ A,
                                __half* __restrict__ O, int total) {
    int i = blockIdx.x * blockDim.x + threadIdx.x;
    if (i >= total) return;
    O[i] = __float2half(A[i]);
}

__global__ void conv_transpose_all_kernel(const float* __restrict__ Wq,
                                          const float* __restrict__ Wk,
                                          const float* __restrict__ Wv,
                                          const float* __restrict__ Wo,
                                          __half* __restrict__ Wqkvt,
                                          __half* __restrict__ Wot) {
    __shared__ float tile[32][33];
    const int z = blockIdx.z;
    const float* W;
    __half* T;
    int N;
    if (z == 0)      { W = Wq; T = Wqkvt;                       N = 2048; }
    else if (z == 1) { W = Wk; T = Wqkvt + (size_t)2048 * E_;   N = 512; }
    else if (z == 2) { W = Wv; T = Wqkvt + (size_t)2560 * E_;   N = 512; }
    else             { W = Wo; T = Wot;                         N = 2048; }
    int n0 = blockIdx.x * 32;
    if (n0 >= N) return;
    int k0 = blockIdx.y * 32;
    int tx = threadIdx.x & 31, ty = threadIdx.x >> 5;
#pragma unroll
    for (int i = 0; i < 32; i += 8)
        tile[ty + i][tx] = W[(size_t)(k0 + ty + i) * N + n0 + tx];
    __syncthreads();
#pragma unroll
    for (int i = 0; i < 32; i += 8)
        T[(size_t)(n0 + ty + i) * E_ + k0 + tx] = __float2half(tile[tx][ty + i]);
}

// ---------------------------------------------------------------------------
// RoPE tables
// ---------------------------------------------------------------------------
__global__ void build_tables_kernel() {
    int idx = blockIdx.x * blockDim.x + threadIdx.x;
    if (idx >= S_ * 64) return;
    int i = idx & 63;
    int s = idx >> 6;
    double inv = pow(10000.0, -(double)i / 64.0);
    double ang = (double)s * inv;
    g_cos[idx] = (float)cos(ang);
    g_sin[idx] = (float)sin(ang);
}

// ---------------------------------------------------------------------------
// Flash attention (validated R11-R14); epilogue writes single fp16.
// ---------------------------------------------------------------------------
#define ATT_SMEM 131072
#define KV_BUF(buf) (65536 + (buf) * 32768)

__global__ void __launch_bounds__(256, 1)
attn3_kernel(const __half* __restrict__ qbh, const __half* __restrict__ qbl,
             const __half* __restrict__ kb, const __half* __restrict__ vt,
             __half* __restrict__ oh) {
    extern __shared__ char smem[];
    const uint32_t sb = smem_u32(smem);
    const int qt = (int)gridDim.x - 1 - (int)blockIdx.x;
    const int h = blockIdx.y, b = blockIdx.z;
    const int kvh = h >> 2;
    const int t = threadIdx.x, lane = t & 31, w = t >> 5;
    const int q0 = qt * 128;
    const int kt_end = q0 + 128;

    auto load_kv = [&](int kt, int buf) {
        const uint32_t kvb = sb + KV_BUF(buf);
#pragma unroll
        for (int j = 0; j < 4; j++) {
            int idx = t + j * 256;
            int dc = idx >> 8, rem = idx & 255;
            int r = rem >> 2, c = rem & 3;
            const __half* src =
                kb + (size_t)(b * S_ + kt + r) * (KV_ * D_) + kvh * 128 + dc * 32 + c * 8;
            CP16(kvb + dc * 4096 + swz(r, c), src);
        }
#pragma unroll
        for (int j = 0; j < 4; j++) {
            int idx = t + j * 256;
            int kc = idx >> 9, rem = idx & 511;
            int r = rem >> 2, c = rem & 3;
            const __half* src =
                vt + (size_t)((b * KV_ + kvh) * 128 + r) * S_ + kt + kc * 32 + c * 8;
            CP16(kvb + 16384 + kc * 8192 + swz(r, c), src);
        }
    };

    {
        const __half* srcs[2] = { qbh, qbl };
#pragma unroll
        for (int j = 0; j < 16; j++) {
            int idx = t + j * 256;
            int prec = idx >> 11, rem = idx & 2047;
            int dc = rem >> 9, rem2 = rem & 511;
            int r = rem2 >> 2, c = rem2 & 3;
            const __half* src =
                srcs[prec] + (size_t)(b * S_ + q0 + r) * (H_ * D_) + h * 128 + dc * 32 + c * 8;
            CP16(sb + (prec * 4 + dc) * 8192 + swz(r, c), src);
        }
        load_kv(0, 0);
        CP_COMMIT();
    }

    float o_acc[16][4];
#pragma unroll
    for (int i = 0; i < 16; i++)
#pragma unroll
        for (int u = 0; u < 4; u++) o_acc[i][u] = 0.f;
    float m0 = -INFINITY, m1 = -INFINITY, l0 = 0.f, l1 = 0.f;

    for (int kt = 0; kt < kt_end; kt += 64) {
        const int ti = kt >> 6;
        if (kt + 64 < kt_end) load_kv(kt + 64, (ti + 1) & 1);
        CP_COMMIT();
        CP_WAIT1();
        __syncthreads();

        const uint32_t kvb = sb + KV_BUF(ti & 1);

        float sf[8][4];
#pragma unroll
        for (int nt = 0; nt < 8; nt++)
#pragma unroll
            for (int u = 0; u < 4; u++) sf[nt][u] = 0.f;

#pragma unroll
        for (int j = 0; j < 8; j++) {
            int dc = j >> 1, ks = j & 1;
            uint32_t ah[4], al[4];
            uint32_t aoff = swz(w * 16 + (lane & 15), ks * 2 + (lane >> 4));
            ldsm4(ah, sb + (0 * 4 + dc) * 8192 + aoff);
            ldsm4(al, sb + (1 * 4 + dc) * 8192 + aoff);
            uint32_t bf[8][2];
#pragma unroll
            for (int np = 0; np < 4; np++) {
                uint32_t boff = swz(np * 16 + ((lane >> 4) << 3) + (lane & 7),
                                    ks * 2 + ((lane >> 3) & 1));
                uint32_t r4[4];
                ldsm4(r4, kvb + dc * 4096 + boff);
                bf[np * 2][0] = r4[0]; bf[np * 2][1] = r4[1];
                bf[np * 2 + 1][0] = r4[2]; bf[np * 2 + 1][1] = r4[3];
            }
#pragma unroll
            for (int nt = 0; nt < 8; nt++)
                mma16816h(sf[nt], ah, bf[nt]);
#pragma unroll
            for (int nt = 0; nt < 8; nt++)
                mma16816h(sf[nt], al, bf[nt]);
        }

        if (kt + 63 > q0 + w * 16) {
            int row0g = q0 + w * 16 + (lane >> 2);
            int colb = kt + ((lane & 3) << 1);
#pragma unroll
            for (int nt = 0; nt < 8; nt++) {
                int c0 = colb + nt * 8;
                if (c0 > row0g)     sf[nt][0] = -INFINITY;
                if (c0 + 1 > row0g) sf[nt][1] = -INFINITY;
                if (c0 > row0g + 8)     sf[nt][2] = -INFINITY;
                if (c0 + 1 > row0g + 8) sf[nt][3] = -INFINITY;
            }
        }

        float mx0 = -INFINITY, mx1 = -INFINITY;
#pragma unroll
        for (int nt = 0; nt < 8; nt++) {
            mx0 = fmaxf(mx0, fmaxf(sf[nt][0], sf[nt][1]));
            mx1 = fmaxf(mx1, fmaxf(sf[nt][2], sf[nt][3]));
        }
        mx0 = fmaxf(mx0, __shfl_xor_sync(0xffffffffu, mx0, 1));
        mx0 = fmaxf(mx0, __shfl_xor_sync(0xffffffffu, mx0, 2));
        mx1 = fmaxf(mx1, __shfl_xor_sync(0xffffffffu, mx1, 1));
        mx1 = fmaxf(mx1, __shfl_xor_sync(0xffffffffu, mx1, 2));
        float mn0 = fmaxf(m0, mx0), mn1 = fmaxf(m1, mx1);
        float corr0 = __expf(m0 - mn0), corr1 = __expf(m1 - mn1);
        float sum0 = 0.f, sum1 = 0.f;
#pragma unroll
        for (int nt = 0; nt < 8; nt++) {
            float p0 = __expf(sf[nt][0] - mn0); sf[nt][0] = p0; sum0 += p0;
            float p1 = __expf(sf[nt][1] - mn0); sf[nt][1] = p1; sum0 += p1;
            float p2 = __expf(sf[nt][2] - mn1); sf[nt][2] = p2; sum1 += p2;
            float p3 = __expf(sf[nt][3] - mn1); sf[nt][3] = p3; sum1 += p3;
        }
        sum0 += __shfl_xor_sync(0xffffffffu, sum0, 1);
        sum0 += __shfl_xor_sync(0xffffffffu, sum0, 2);
        sum1 += __shfl_xor_sync(0xffffffffu, sum1, 1);
        sum1 += __shfl_xor_sync(0xffffffffu, sum1, 2);
        l0 = l0 * corr0 + sum0;
        l1 = l1 * corr1 + sum1;
        m0 = mn0; m1 = mn1;
#pragma unroll
        for (int i = 0; i < 16; i++) {
            o_acc[i][0] *= corr0; o_acc[i][1] *= corr0;
            o_acc[i][2] *= corr1; o_acc[i][3] *= corr1;
        }

#pragma unroll
        for (int s4 = 0; s4 < 4; s4++) {
            uint32_t ah[4], al[4];
#pragma unroll
            for (int half = 0; half < 2; half++) {
                const float* pp = sf[2 * s4 + half];
                float h0f = __half2float(__float2half(pp[0]));
                float h1f = __half2float(__float2half(pp[1]));
                float h2f = __half2float(__float2half(pp[2]));
                float h3f = __half2float(__float2half(pp[3]));
                ah[half * 2 + 0] = pack_h16x2(h0f, h1f);
                ah[half * 2 + 1] = pack_h16x2(h2f, h3f);
                al[half * 2 + 0] = pack_h16x2(pp[0] - h0f, pp[1] - h1f);
                al[half * 2 + 1] = pack_h16x2(pp[2] - h2f, pp[3] - h3f);
            }
            int kc = s4 >> 1;
            uint32_t chunk = (uint32_t)((s4 & 1) * 2 + ((lane >> 3) & 1));
            uint32_t vb[8][4];
#pragma unroll
            for (int np = 0; np < 8; np++) {
                uint32_t boff = swz(np * 16 + ((lane >> 4) << 3) + (lane & 7), chunk);
                ldsm4(vb[np], kvb + 16384 + kc * 8192 + boff);
            }
#pragma unroll
            for (int np = 0; np < 8; np++) {
                mma16816h(o_acc[np * 2], ah, vb[np]);
                mma16816h(o_acc[np * 2 + 1], ah, vb[np] + 2);
            }
#pragma unroll
            for (int np = 0; np < 8; np++) {
                mma16816h(o_acc[np * 2], al, vb[np]);
                mma16816h(o_acc[np * 2 + 1], al, vb[np] + 2);
            }
        }
        __syncthreads();
    }

    // epilogue: normalize, write single fp16 (Wo GEMM A-operand)
    float inv0 = 1.f / l0, inv1 = 1.f / l1;
    int row0g = q0 + w * 16 + (lane >> 2);
    size_t base0 = (size_t)(b * S_ + row0g) * (H_ * D_) + h * 128 + ((lane & 3) << 1);
    size_t base1 = base0 + 8 * (size_t)(H_ * D_);
#pragma unroll
    for (int nt = 0; nt < 16; nt++) {
        *(uint32_t*)(oh + base0 + nt * 8) =
            pack_h16x2(o_acc[nt][0] * inv0, o_acc[nt][1] * inv0);
        *(uint32_t*)(oh + base1 + nt * 8) =
            pack_h16x2(o_acc[nt][2] * inv1, o_acc[nt][3] * inv1);
    }
}

// ---------------------------------------------------------------------------
// Launch
// ---------------------------------------------------------------------------
extern "C" void kernel_launch(void* const* d_in, const int* in_sizes, int n_in,
                              void* d_out, int out_size) {
    const float *x, *Wq, *Wk, *Wv, *Wo;
    if (in_sizes[0] == NTOK * E_) {
        x  = (const float*)d_in[0];
        Wq = (const float*)d_in[1];
        Wk = (const float*)d_in[2];
        Wv = (const float*)d_in[3];
        Wo = (const float*)d_in[4];
    } else {
        Wk = (const float*)d_in[0];
        Wo = (const float*)d_in[1];
        Wq = (const float*)d_in[2];
        Wv = (const float*)d_in[3];
        x  = (const float*)d_in[4];
    }
    float* out = (float*)d_out;

    __half *x16, *o16, *qbh, *qbl, *kb, *vt, *Wqkvt16, *Wot16;
    cudaGetSymbolAddress((void**)&x16, g_x16);
    cudaGetSymbolAddress((void**)&o16, g_o16);
    cudaGetSymbolAddress((void**)&qbh, g_qb16h);
    cudaGetSymbolAddress((void**)&qbl, g_qb16l);
    cudaGetSymbolAddress((void**)&kb, g_kb16);
    cudaGetSymbolAddress((void**)&vt, g_vt16);
    cudaGetSymbolAddress((void**)&Wqkvt16, g_Wqkvt16);
    cudaGetSymbolAddress((void**)&Wot16, g_Wot16);

    cudaFuncSetAttribute(f16gemm_kernel, cudaFuncAttributeMaxDynamicSharedMemorySize, FG_SMEM);
    cudaFuncSetAttribute(qkvgemm_kernel, cudaFuncAttributeMaxDynamicSharedMemorySize, QKV_SMEM);
    cudaFuncSetAttribute(attn3_kernel, cudaFuncAttributeMaxDynamicSharedMemorySize, ATT_SMEM);

    build_tables_kernel<<<(S_ * 64 + 255) / 256, 256>>>();
    conv_f16_kernel<<<(NTOK * E_ + 255) / 256, 256>>>(x, x16, NTOK * E_);
    {
        dim3 g(E_ / 32, E_ / 32, 4);
        conv_transpose_all_kernel<<<g, 256>>>(Wq, Wk, Wv, Wo, Wqkvt16, Wot16);
    }
    {
        dim3 g(NQKV / 128, NTOK / 128);
        qkvgemm_kernel<<<g, 256, QKV_SMEM>>>(x16, Wqkvt16, qbh, qbl, kb, vt);
    }
    {
        dim3 ga(S_ / 128, H_, B_);
        attn3_kernel<<<ga, 256, ATT_SMEM>>>(qbh, qbl, kb, vt, o16);
    }
    {
        dim3 go(E_ / 128, NTOK / 128);
        f16gemm_kernel<<<go, 256, FG_SMEM>>>(o16, Wot16, out, NTOK, E_, E_);
    }
}

// round 16
// speedup vs baseline: 1.6855x; 1.2867x over previous
#include <cuda_runtime.h>
#include <cuda_bf16.h>
#include <cuda_fp16.h>
#include <math.h>
#include <stdint.h>

// Problem constants
#define B_  2
#define S_  2048
#define E_  2048
#define H_  16
#define KV_ 4
#define G_  (H_ / KV_)   // 4
#define D_  128
#define NTOK (B_ * S_)   // 4096
#define NQKV 3072

// ---------------------------------------------------------------------------
// Scratch (device globals)
// ---------------------------------------------------------------------------
__device__ float g_cos[S_ * 64];
__device__ float g_sin[S_ * 64];

__device__ __half g_x16[NTOK * E_];
__device__ __half g_o16[NTOK * (H_ * D_)];
__device__ __half g_qb16h[NTOK * (H_ * D_)];
__device__ __half g_qb16l[NTOK * (H_ * D_)];
__device__ __half g_kb16[NTOK * (KV_ * D_)];
__device__ __half g_vt16[B_ * KV_ * D_ * S_];
__device__ __half g_Wqkvt16[NQKV * E_];
__device__ __half g_Wot16[E_ * E_];

// ---------------------------------------------------------------------------
// Tensor-core helpers (baseline ISA)
// ---------------------------------------------------------------------------
__device__ __forceinline__ uint32_t smem_u32(const void* p) {
    uint32_t a;
    asm("{ .reg .u64 t; cvta.to.shared.u64 t, %1; cvt.u32.u64 %0, t; }" : "=r"(a) : "l"(p));
    return a;
}

__device__ __forceinline__ void ldsm4(uint32_t* r, uint32_t addr) {
    asm volatile("ldmatrix.sync.aligned.m8n8.x4.shared.b16 {%0,%1,%2,%3}, [%4];"
                 : "=r"(r[0]), "=r"(r[1]), "=r"(r[2]), "=r"(r[3]) : "r"(addr));
}

__device__ __forceinline__ void mma16816h(float* d, const uint32_t* a, const uint32_t* b) {
    asm volatile(
        "mma.sync.aligned.m16n8k16.row.col.f32.f16.f16.f32 "
        "{%0,%1,%2,%3}, {%4,%5,%6,%7}, {%8,%9}, {%0,%1,%2,%3};"
        : "+f"(d[0]), "+f"(d[1]), "+f"(d[2]), "+f"(d[3])
        : "r"(a[0]), "r"(a[1]), "r"(a[2]), "r"(a[3]), "r"(b[0]), "r"(b[1]));
}

#define CP16(dst, src) \
    asm volatile("cp.async.cg.shared.global [%0], [%1], 16;" :: "r"(dst), "l"(src))
#define CP_COMMIT() asm volatile("cp.async.commit_group;" ::: "memory")
#define CP_WAIT0() asm volatile("cp.async.wait_group 0;" ::: "memory")
#define CP_WAIT1() asm volatile("cp.async.wait_group 1;" ::: "memory")

__device__ __forceinline__ uint32_t swz(int row, int chunk) {
    return (uint32_t)(row * 64 + ((chunk ^ ((row >> 1) & 3)) << 4));
}

__device__ __forceinline__ uint32_t pack_h16x2(float a, float b) {
    __half2 t = __floats2half2_rn(a, b);   // a -> low
    return *(uint32_t*)&t;
}

// ---------------------------------------------------------------------------
// Single-fp16 GEMM (256 threads, 2 CTAs/SM target).
// ---------------------------------------------------------------------------
#define BKC 32
#define TILE_B 8192
#define BUF1_B (2 * TILE_B)         // 16 KB/stage
#define FG_SMEM (2 * BUF1_B)        // 32 KB

__global__ void __launch_bounds__(256, 2)
f16gemm_kernel(const __half* __restrict__ A, const __half* __restrict__ Bh,
               float* __restrict__ C, int M, int N, int K) {
    extern __shared__ char smem[];
    const uint32_t smem_base = smem_u32(smem);
    const int t = threadIdx.x;
    const int lane = t & 31;
    const int wid = t >> 5;
    const int wm = wid & 1;
    const int wn = wid >> 1;
    const int bm = blockIdx.y * 128;
    const int bn = blockIdx.x * 128;

    const char* srcs[2] = {
        (const char*)(A + (size_t)bm * K),
        (const char*)(Bh + (size_t)bn * K) };

    float acc[4][4][4];
#pragma unroll
    for (int i = 0; i < 4; i++)
#pragma unroll
        for (int j = 0; j < 4; j++)
#pragma unroll
            for (int u = 0; u < 4; u++) acc[i][j][u] = 0.f;

    const int NC = K / BKC;
    const size_t rowb = (size_t)K * 2;

    {
#pragma unroll
        for (int tl = 0; tl < 2; tl++) {
            const char* src = srcs[tl];
            uint32_t dstt = smem_base + tl * TILE_B;
#pragma unroll
            for (int j = 0; j < 2; j++) {
                int idx = t + j * 256;
                int r = idx >> 2, c = idx & 3;
                CP16(dstt + swz(r, c), src + (size_t)r * rowb + c * 16);
            }
        }
        CP_COMMIT();
    }

    for (int ic = 0; ic < NC; ic++) {
        if (ic + 1 < NC) {
            const int k0b = (ic + 1) * BKC * 2;
            uint32_t sbase = smem_base + ((ic + 1) & 1) * BUF1_B;
#pragma unroll
            for (int tl = 0; tl < 2; tl++) {
                const char* src = srcs[tl] + k0b;
                uint32_t dstt = sbase + tl * TILE_B;
#pragma unroll
                for (int j = 0; j < 2; j++) {
                    int idx = t + j * 256;
                    int r = idx >> 2, c = idx & 3;
                    CP16(dstt + swz(r, c), src + (size_t)r * rowb + c * 16);
                }
            }
            CP_COMMIT();
            CP_WAIT1();
        } else {
            CP_WAIT0();
        }
        __syncthreads();

        const uint32_t buf = smem_base + (ic & 1) * BUF1_B;
        const uint32_t a_base = buf;
        const uint32_t b_base = buf + TILE_B;

#pragma unroll
        for (int ks = 0; ks < 2; ks++) {
            uint32_t a_f[4][4];
#pragma unroll
            for (int mt = 0; mt < 4; mt++) {
                int row = wm * 64 + mt * 16 + (lane & 15);
                int chunk = ks * 2 + (lane >> 4);
                ldsm4(a_f[mt], a_base + swz(row, chunk));
            }
            uint32_t b_f[4][2];
#pragma unroll
            for (int np = 0; np < 2; np++) {
                int row = wn * 32 + np * 16 + ((lane >> 4) << 3) + (lane & 7);
                int chunk = ks * 2 + ((lane >> 3) & 1);
                uint32_t r4[4];
                ldsm4(r4, b_base + swz(row, chunk));
                b_f[np * 2][0] = r4[0]; b_f[np * 2][1] = r4[1];
                b_f[np * 2 + 1][0] = r4[2]; b_f[np * 2 + 1][1] = r4[3];
            }
#pragma unroll
            for (int mt = 0; mt < 4; mt++)
#pragma unroll
                for (int nt = 0; nt < 4; nt++)
                    mma16816h(acc[mt][nt], a_f[mt], b_f[nt]);
        }
        __syncthreads();
    }

#pragma unroll
    for (int mt = 0; mt < 4; mt++) {
#pragma unroll
        for (int nt = 0; nt < 4; nt++) {
            int r0 = bm + wm * 64 + mt * 16 + (lane >> 2);
            int col = bn + wn * 32 + nt * 8 + ((lane & 3) << 1);
            float* p0 = C + (size_t)r0 * N + col;
            float* p1 = C + (size_t)(r0 + 8) * N + col;
            p0[0] = acc[mt][nt][0]; p0[1] = acc[mt][nt][1];
            p1[0] = acc[mt][nt][2]; p1[1] = acc[mt][nt][3];
        }
    }
}

// ---------------------------------------------------------------------------
// QKV GEMM; epilogue runs in two 64-row halves so smem = 33 KB -> 2 CTAs/SM.
// ---------------------------------------------------------------------------
#define PS_STRIDE 129
#define EPI_B (64 * PS_STRIDE * 4)           // 33,024 B
#define QKV_SMEM (EPI_B > FG_SMEM ? EPI_B : FG_SMEM)

__global__ void __launch_bounds__(256, 2)
qkvgemm_kernel(const __half* __restrict__ A, const __half* __restrict__ Bh,
               __half* __restrict__ qbh, __half* __restrict__ qbl,
               __half* __restrict__ kb, __half* __restrict__ vt) {
    extern __shared__ char smem[];
    const uint32_t smem_base = smem_u32(smem);
    const int t = threadIdx.x;
    const int lane = t & 31;
    const int wid = t >> 5;
    const int wm = wid & 1;
    const int wn = wid >> 1;
    const int bm = blockIdx.y * 128;
    const int bn = blockIdx.x * 128;
    const int K = E_;

    const char* srcs[2] = {
        (const char*)(A + (size_t)bm * K),
        (const char*)(Bh + (size_t)bn * K) };

    float acc[4][4][4];
#pragma unroll
    for (int i = 0; i < 4; i++)
#pragma unroll
        for (int j = 0; j < 4; j++)
#pragma unroll
            for (int u = 0; u < 4; u++) acc[i][j][u] = 0.f;

    const int NC = K / BKC;
    const size_t rowb = (size_t)K * 2;

    {
#pragma unroll
        for (int tl = 0; tl < 2; tl++) {
            const char* src = srcs[tl];
            uint32_t dstt = smem_base + tl * TILE_B;
#pragma unroll
            for (int j = 0; j < 2; j++) {
                int idx = t + j * 256;
                int r = idx >> 2, c = idx & 3;
                CP16(dstt + swz(r, c), src + (size_t)r * rowb + c * 16);
            }
        }
        CP_COMMIT();
    }

    for (int ic = 0; ic < NC; ic++) {
        if (ic + 1 < NC) {
            const int k0b = (ic + 1) * BKC * 2;
            uint32_t sbase = smem_base + ((ic + 1) & 1) * BUF1_B;
#pragma unroll
            for (int tl = 0; tl < 2; tl++) {
                const char* src = srcs[tl] + k0b;
                uint32_t dstt = sbase + tl * TILE_B;
#pragma unroll
                for (int j = 0; j < 2; j++) {
                    int idx = t + j * 256;
                    int r = idx >> 2, c = idx & 3;
                    CP16(dstt + swz(r, c), src + (size_t)r * rowb + c * 16);
                }
            }
            CP_COMMIT();
            CP_WAIT1();
        } else {
            CP_WAIT0();
        }
        __syncthreads();

        const uint32_t buf = smem_base + (ic & 1) * BUF1_B;
        const uint32_t a_base = buf;
        const uint32_t b_base = buf + TILE_B;

#pragma unroll
        for (int ks = 0; ks < 2; ks++) {
            uint32_t a_f[4][4];
#pragma unroll
            for (int mt = 0; mt < 4; mt++) {
                int row = wm * 64 + mt * 16 + (lane & 15);
                int chunk = ks * 2 + (lane >> 4);
                ldsm4(a_f[mt], a_base + swz(row, chunk));
            }
            uint32_t b_f[4][2];
#pragma unroll
            for (int np = 0; np < 2; np++) {
                int row = wn * 32 + np * 16 + ((lane >> 4) << 3) + (lane & 7);
                int chunk = ks * 2 + ((lane >> 3) & 1);
                uint32_t r4[4];
                ldsm4(r4, b_base + swz(row, chunk));
                b_f[np * 2][0] = r4[0]; b_f[np * 2][1] = r4[1];
                b_f[np * 2 + 1][0] = r4[2]; b_f[np * 2 + 1][1] = r4[3];
            }
#pragma unroll
            for (int mt = 0; mt < 4; mt++)
#pragma unroll
                for (int nt = 0; nt < 4; nt++)
                    mma16816h(acc[mt][nt], a_f[mt], b_f[nt]);
        }
        __syncthreads();
    }

    // ---- fused epilogue, two 64-row halves (smem = 64 x PS_STRIDE floats) ----
    float* ps = (float*)smem;
    const float scale = 0.08838834764831845f;
#pragma unroll
    for (int half = 0; half < 2; half++) {
        __syncthreads();
        if (wm == half) {
#pragma unroll
            for (int mt = 0; mt < 4; mt++) {
#pragma unroll
                for (int nt = 0; nt < 4; nt++) {
                    int r0 = mt * 16 + (lane >> 2);       // local row in half
                    int col = wn * 32 + nt * 8 + ((lane & 3) << 1);
                    ps[r0 * PS_STRIDE + col]       = acc[mt][nt][0];
                    ps[r0 * PS_STRIDE + col + 1]   = acc[mt][nt][1];
                    ps[(r0 + 8) * PS_STRIDE + col]     = acc[mt][nt][2];
                    ps[(r0 + 8) * PS_STRIDE + col + 1] = acc[mt][nt][3];
                }
            }
        }
        __syncthreads();

        const int rowbase = bm + half * 64;
        if (bn < 2048) {
            const int h = bn >> 7;
            for (int idx = t; idx < 64 * 64; idx += 256) {
                int r = idx >> 6, i = idx & 63;
                int tok = rowbase + r;
                int s = tok & (S_ - 1);
                float c  = g_cos[s * 64 + i];
                float sn = g_sin[s * 64 + i];
                float v1 = ps[r * PS_STRIDE + i];
                float v2 = ps[r * PS_STRIDE + 64 + i];
                float r1 = (v1 * c - v2 * sn) * scale;
                float r2 = (v2 * c + v1 * sn) * scale;
                __half h1 = __float2half(r1);
                __half h2 = __float2half(r2);
                size_t dst = (size_t)tok * (H_ * D_) + h * 128;
                qbh[dst + i] = h1;
                qbl[dst + i] = __float2half(r1 - __half2float(h1));
                qbh[dst + 64 + i] = h2;
                qbl[dst + 64 + i] = __float2half(r2 - __half2float(h2));
            }
        } else if (bn < 2560) {
            const int kvh = (bn - 2048) >> 7;
            for (int idx = t; idx < 64 * 64; idx += 256) {
                int r = idx >> 6, i = idx & 63;
                int tok = rowbase + r;
                int s = tok & (S_ - 1);
                float c  = g_cos[s * 64 + i];
                float sn = g_sin[s * 64 + i];
                float v1 = ps[r * PS_STRIDE + i];
                float v2 = ps[r * PS_STRIDE + 64 + i];
                size_t dst = (size_t)tok * (KV_ * D_) + kvh * 128;
                kb[dst + i]      = __float2half(v1 * c - v2 * sn);
                kb[dst + 64 + i] = __float2half(v2 * c + v1 * sn);
            }
        } else {
            const int kvh = (bn - 2560) >> 7;
            const int b = bm >> 11;
            for (int idx = t; idx < 64 * 128; idx += 256) {
                int d = idx >> 6, rr = idx & 63;
                int tok = rowbase + rr;
                int s = tok & (S_ - 1);
                vt[(size_t)((b * KV_ + kvh) * 128 + d) * S_ + s] =
                    __float2half(ps[rr * PS_STRIDE + d]);
            }
        }
    }
}

// ---------------------------------------------------------------------------
// Conversions
// ---------------------------------------------------------------------------
__global__ void conv_f16_kernel(const float* __restrict__ A,
                                __half* __restrict__ O, int total) {
    int i = blockIdx.x * blockDim.x + threadIdx.x;
    if (i >= total) return;
    O[i] = __float2half(A[i]);
}

__global__ void conv_transpose_all_kernel(const float* __restrict__ Wq,
                                          const float* __restrict__ Wk,
                                          const float* __restrict__ Wv,
                                          const float* __restrict__ Wo,
                                          __half* __restrict__ Wqkvt,
                                          __half* __restrict__ Wot) {
    __shared__ float tile[32][33];
    const int z = blockIdx.z;
    const float* W;
    __half* T;
    int N;
    if (z == 0)      { W = Wq; T = Wqkvt;                       N = 2048; }
    else if (z == 1) { W = Wk; T = Wqkvt + (size_t)2048 * E_;   N = 512; }
    else if (z == 2) { W = Wv; T = Wqkvt + (size_t)2560 * E_;   N = 512; }
    else             { W = Wo; T = Wot;                         N = 2048; }
    int n0 = blockIdx.x * 32;
    if (n0 >= N) return;
    int k0 = blockIdx.y * 32;
    int tx = threadIdx.x & 31, ty = threadIdx.x >> 5;
#pragma unroll
    for (int i = 0; i < 32; i += 8)
        tile[ty + i][tx] = W[(size_t)(k0 + ty + i) * N + n0 + tx];
    __syncthreads();
#pragma unroll
    for (int i = 0; i < 32; i += 8)
        T[(size_t)(n0 + ty + i) * E_ + k0 + tx] = __float2half(tile[tx][ty + i]);
}

// ---------------------------------------------------------------------------
// RoPE tables
// ---------------------------------------------------------------------------
__global__ void build_tables_kernel() {
    int idx = blockIdx.x * blockDim.x + threadIdx.x;
    if (idx >= S_ * 64) return;
    int i = idx & 63;
    int s = idx >> 6;
    double inv = pow(10000.0, -(double)i / 64.0);
    double ang = (double)s * inv;
    g_cos[idx] = (float)cos(ang);
    g_sin[idx] = (float)sin(ang);
}

// ---------------------------------------------------------------------------
// Flash attention: Q hi/lo x K single; P single x V single (P-lo dropped).
// ---------------------------------------------------------------------------
#define ATT_SMEM 131072
#define KV_BUF(buf) (65536 + (buf) * 32768)

__global__ void __launch_bounds__(256, 1)
attn3_kernel(const __half* __restrict__ qbh, const __half* __restrict__ qbl,
             const __half* __restrict__ kb, const __half* __restrict__ vt,
             __half* __restrict__ oh) {
    extern __shared__ char smem[];
    const uint32_t sb = smem_u32(smem);
    const int qt = (int)gridDim.x - 1 - (int)blockIdx.x;
    const int h = blockIdx.y, b = blockIdx.z;
    const int kvh = h >> 2;
    const int t = threadIdx.x, lane = t & 31, w = t >> 5;
    const int q0 = qt * 128;
    const int kt_end = q0 + 128;

    auto load_kv = [&](int kt, int buf) {
        const uint32_t kvb = sb + KV_BUF(buf);
#pragma unroll
        for (int j = 0; j < 4; j++) {
            int idx = t + j * 256;
            int dc = idx >> 8, rem = idx & 255;
            int r = rem >> 2, c = rem & 3;
            const __half* src =
                kb + (size_t)(b * S_ + kt + r) * (KV_ * D_) + kvh * 128 + dc * 32 + c * 8;
            CP16(kvb + dc * 4096 + swz(r, c), src);
        }
#pragma unroll
        for (int j = 0; j < 4; j++) {
            int idx = t + j * 256;
            int kc = idx >> 9, rem = idx & 511;
            int r = rem >> 2, c = rem & 3;
            const __half* src =
                vt + (size_t)((b * KV_ + kvh) * 128 + r) * S_ + kt + kc * 32 + c * 8;
            CP16(kvb + 16384 + kc * 8192 + swz(r, c), src);
        }
    };

    {
        const __half* srcs[2] = { qbh, qbl };
#pragma unroll
        for (int j = 0; j < 16; j++) {
            int idx = t + j * 256;
            int prec = idx >> 11, rem = idx & 2047;
            int dc = rem >> 9, rem2 = rem & 511;
            int r = rem2 >> 2, c = rem2 & 3;
            const __half* src =
                srcs[prec] + (size_t)(b * S_ + q0 + r) * (H_ * D_) + h * 128 + dc * 32 + c * 8;
            CP16(sb + (prec * 4 + dc) * 8192 + swz(r, c), src);
        }
        load_kv(0, 0);
        CP_COMMIT();
    }

    float o_acc[16][4];
#pragma unroll
    for (int i = 0; i < 16; i++)
#pragma unroll
        for (int u = 0; u < 4; u++) o_acc[i][u] = 0.f;
    float m0 = -INFINITY, m1 = -INFINITY, l0 = 0.f, l1 = 0.f;

    for (int kt = 0; kt < kt_end; kt += 64) {
        const int ti = kt >> 6;
        if (kt + 64 < kt_end) load_kv(kt + 64, (ti + 1) & 1);
        CP_COMMIT();
        CP_WAIT1();
        __syncthreads();

        const uint32_t kvb = sb + KV_BUF(ti & 1);

        float sf[8][4];
#pragma unroll
        for (int nt = 0; nt < 8; nt++)
#pragma unroll
            for (int u = 0; u < 4; u++) sf[nt][u] = 0.f;

#pragma unroll
        for (int j = 0; j < 8; j++) {
            int dc = j >> 1, ks = j & 1;
            uint32_t ah[4], al[4];
            uint32_t aoff = swz(w * 16 + (lane & 15), ks * 2 + (lane >> 4));
            ldsm4(ah, sb + (0 * 4 + dc) * 8192 + aoff);
            ldsm4(al, sb + (1 * 4 + dc) * 8192 + aoff);
            uint32_t bf[8][2];
#pragma unroll
            for (int np = 0; np < 4; np++) {
                uint32_t boff = swz(np * 16 + ((lane >> 4) << 3) + (lane & 7),
                                    ks * 2 + ((lane >> 3) & 1));
                uint32_t r4[4];
                ldsm4(r4, kvb + dc * 4096 + boff);
                bf[np * 2][0] = r4[0]; bf[np * 2][1] = r4[1];
                bf[np * 2 + 1][0] = r4[2]; bf[np * 2 + 1][1] = r4[3];
            }
#pragma unroll
            for (int nt = 0; nt < 8; nt++)
                mma16816h(sf[nt], ah, bf[nt]);
#pragma unroll
            for (int nt = 0; nt < 8; nt++)
                mma16816h(sf[nt], al, bf[nt]);
        }

        if (kt + 63 > q0 + w * 16) {
            int row0g = q0 + w * 16 + (lane >> 2);
            int colb = kt + ((lane & 3) << 1);
#pragma unroll
            for (int nt = 0; nt < 8; nt++) {
                int c0 = colb + nt * 8;
                if (c0 > row0g)     sf[nt][0] = -INFINITY;
                if (c0 + 1 > row0g) sf[nt][1] = -INFINITY;
                if (c0 > row0g + 8)     sf[nt][2] = -INFINITY;
                if (c0 + 1 > row0g + 8) sf[nt][3] = -INFINITY;
            }
        }

        float mx0 = -INFINITY, mx1 = -INFINITY;
#pragma unroll
        for (int nt = 0; nt < 8; nt++) {
            mx0 = fmaxf(mx0, fmaxf(sf[nt][0], sf[nt][1]));
            mx1 = fmaxf(mx1, fmaxf(sf[nt][2], sf[nt][3]));
        }
        mx0 = fmaxf(mx0, __shfl_xor_sync(0xffffffffu, mx0, 1));
        mx0 = fmaxf(mx0, __shfl_xor_sync(0xffffffffu, mx0, 2));
        mx1 = fmaxf(mx1, __shfl_xor_sync(0xffffffffu, mx1, 1));
        mx1 = fmaxf(mx1, __shfl_xor_sync(0xffffffffu, mx1, 2));
        float mn0 = fmaxf(m0, mx0), mn1 = fmaxf(m1, mx1);
        float corr0 = __expf(m0 - mn0), corr1 = __expf(m1 - mn1);
        float sum0 = 0.f, sum1 = 0.f;
#pragma unroll
        for (int nt = 0; nt < 8; nt++) {
            float p0 = __expf(sf[nt][0] - mn0); sf[nt][0] = p0; sum0 += p0;
            float p1 = __expf(sf[nt][1] - mn0); sf[nt][1] = p1; sum0 += p1;
            float p2 = __expf(sf[nt][2] - mn1); sf[nt][2] = p2; sum1 += p2;
            float p3 = __expf(sf[nt][3] - mn1); sf[nt][3] = p3; sum1 += p3;
        }
        sum0 += __shfl_xor_sync(0xffffffffu, sum0, 1);
        sum0 += __shfl_xor_sync(0xffffffffu, sum0, 2);
        sum1 += __shfl_xor_sync(0xffffffffu, sum1, 1);
        sum1 += __shfl_xor_sync(0xffffffffu, sum1, 2);
        l0 = l0 * corr0 + sum0;
        l1 = l1 * corr1 + sum1;
        m0 = mn0; m1 = mn1;
#pragma unroll
        for (int i = 0; i < 16; i++) {
            o_acc[i][0] *= corr0; o_acc[i][1] *= corr0;
            o_acc[i][2] *= corr1; o_acc[i][3] *= corr1;
        }

        // ---- PV: single-fp16 P x single-fp16 V ----
#pragma unroll
        for (int s4 = 0; s4 < 4; s4++) {
            uint32_t ap[4];
#pragma unroll
            for (int half = 0; half < 2; half++) {
                const float* pp = sf[2 * s4 + half];
                ap[half * 2 + 0] = pack_h16x2(pp[0], pp[1]);
                ap[half * 2 + 1] = pack_h16x2(pp[2], pp[3]);
            }
            int kc = s4 >> 1;
            uint32_t chunk = (uint32_t)((s4 & 1) * 2 + ((lane >> 3) & 1));
            uint32_t vb[8][4];
#pragma unroll
            for (int np = 0; np < 8; np++) {
                uint32_t boff = swz(np * 16 + ((lane >> 4) << 3) + (lane & 7), chunk);
                ldsm4(vb[np], kvb + 16384 + kc * 8192 + boff);
            }
#pragma unroll
            for (int np = 0; np < 8; np++) {
                mma16816h(o_acc[np * 2], ap, vb[np]);
                mma16816h(o_acc[np * 2 + 1], ap, vb[np] + 2);
            }
        }
        __syncthreads();
    }

    float inv0 = 1.f / l0, inv1 = 1.f / l1;
    int row0g = q0 + w * 16 + (lane >> 2);
    size_t base0 = (size_t)(b * S_ + row0g) * (H_ * D_) + h * 128 + ((lane & 3) << 1);
    size_t base1 = base0 + 8 * (size_t)(H_ * D_);
#pragma unroll
    for (int nt = 0; nt < 16; nt++) {
        *(uint32_t*)(oh + base0 + nt * 8) =
            pack_h16x2(o_acc[nt][0] * inv0, o_acc[nt][1] * inv0);
        *(uint32_t*)(oh + base1 + nt * 8) =
            pack_h16x2(o_acc[nt][2] * inv1, o_acc[nt][3] * inv1);
    }
}

// ---------------------------------------------------------------------------
// Launch
// ---------------------------------------------------------------------------
extern "C" void kernel_launch(void* const* d_in, const int* in_sizes, int n_in,
                              void* d_out, int out_size) {
    const float *x, *Wq, *Wk, *Wv, *Wo;
    if (in_sizes[0] == NTOK * E_) {
        x  = (const float*)d_in[0];
        Wq = (const float*)d_in[1];
        Wk = (const float*)d_in[2];
        Wv = (const float*)d_in[3];
        Wo = (const float*)d_in[4];
    } else {
        Wk = (const float*)d_in[0];
        Wo = (const float*)d_in[1];
        Wq = (const float*)d_in[2];
        Wv = (const float*)d_in[3];
        x  = (const float*)d_in[4];
    }
    float* out = (float*)d_out;

    __half *x16, *o16, *qbh, *qbl, *kb, *vt, *Wqkvt16, *Wot16;
    cudaGetSymbolAddress((void**)&x16, g_x16);
    cudaGetSymbolAddress((void**)&o16, g_o16);
    cudaGetSymbolAddress((void**)&qbh, g_qb16h);
    cudaGetSymbolAddress((void**)&qbl, g_qb16l);
    cudaGetSymbolAddress((void**)&kb, g_kb16);
    cudaGetSymbolAddress((void**)&vt, g_vt16);
    cudaGetSymbolAddress((void**)&Wqkvt16, g_Wqkvt16);
    cudaGetSymbolAddress((void**)&Wot16, g_Wot16);

    cudaFuncSetAttribute(f16gemm_kernel, cudaFuncAttributeMaxDynamicSharedMemorySize, FG_SMEM);
    cudaFuncSetAttribute(qkvgemm_kernel, cudaFuncAttributeMaxDynamicSharedMemorySize, QKV_SMEM);
    cudaFuncSetAttribute(attn3_kernel, cudaFuncAttributeMaxDynamicSharedMemorySize, ATT_SMEM);

    build_tables_kernel<<<(S_ * 64 + 255) / 256, 256>>>();
    conv_f16_kernel<<<(NTOK * E_ + 255) / 256, 256>>>(x, x16, NTOK * E_);
    {
        dim3 g(E_ / 32, E_ / 32, 4);
        conv_transpose_all_kernel<<<g, 256>>>(Wq, Wk, Wv, Wo, Wqkvt16, Wot16);
    }
    {
        dim3 g(NQKV / 128, NTOK / 128);
        qkvgemm_kernel<<<g, 256, QKV_SMEM>>>(x16, Wqkvt16, qbh, qbl, kb, vt);
    }
    {
        dim3 ga(S_ / 128, H_, B_);
        attn3_kernel<<<ga, 256, ATT_SMEM>>>(qbh, qbl, kb, vt, o16);
    }
    {
        dim3 go(E_ / 128, NTOK / 128);
        f16gemm_kernel<<<go, 256, FG_SMEM>>>(o16, Wot16, out, NTOK, E_, E_);
    }
}

// round 17
// speedup vs baseline: 1.7994x; 1.0676x over previous
#include <cuda_runtime.h>
#include <cuda_bf16.h>
#include <cuda_fp16.h>
#include <math.h>
#include <stdint.h>

// Problem constants
#define B_  2
#define S_  2048
#define E_  2048
#define H_  16
#define KV_ 4
#define G_  (H_ / KV_)   // 4
#define D_  128
#define NTOK (B_ * S_)   // 4096
#define NQKV 3072

// ---------------------------------------------------------------------------
// Scratch (device globals)
// ---------------------------------------------------------------------------
__device__ float g_cos[S_ * 64];
__device__ float g_sin[S_ * 64];

__device__ __half g_x16[NTOK * E_];
__device__ __half g_o16[NTOK * (H_ * D_)];
__device__ __half g_qb16[NTOK * (H_ * D_)];     // Q post-rope single fp16
__device__ __half g_kb16[NTOK * (KV_ * D_)];    // K post-rope single
__device__ __half g_vt16[B_ * KV_ * D_ * S_];   // V transposed single
__device__ __half g_Wqkvt16[NQKV * E_];
__device__ __half g_Wot16[E_ * E_];

// ---------------------------------------------------------------------------
// Tensor-core helpers (baseline ISA)
// ---------------------------------------------------------------------------
__device__ __forceinline__ uint32_t smem_u32(const void* p) {
    uint32_t a;
    asm("{ .reg .u64 t; cvta.to.shared.u64 t, %1; cvt.u32.u64 %0, t; }" : "=r"(a) : "l"(p));
    return a;
}

__device__ __forceinline__ void ldsm4(uint32_t* r, uint32_t addr) {
    asm volatile("ldmatrix.sync.aligned.m8n8.x4.shared.b16 {%0,%1,%2,%3}, [%4];"
                 : "=r"(r[0]), "=r"(r[1]), "=r"(r[2]), "=r"(r[3]) : "r"(addr));
}

__device__ __forceinline__ void mma16816h(float* d, const uint32_t* a, const uint32_t* b) {
    asm volatile(
        "mma.sync.aligned.m16n8k16.row.col.f32.f16.f16.f32 "
        "{%0,%1,%2,%3}, {%4,%5,%6,%7}, {%8,%9}, {%0,%1,%2,%3};"
        : "+f"(d[0]), "+f"(d[1]), "+f"(d[2]), "+f"(d[3])
        : "r"(a[0]), "r"(a[1]), "r"(a[2]), "r"(a[3]), "r"(b[0]), "r"(b[1]));
}

#define CP16(dst, src) \
    asm volatile("cp.async.cg.shared.global [%0], [%1], 16;" :: "r"(dst), "l"(src))
#define CP_COMMIT() asm volatile("cp.async.commit_group;" ::: "memory")
#define CP_WAIT0() asm volatile("cp.async.wait_group 0;" ::: "memory")
#define CP_WAIT1() asm volatile("cp.async.wait_group 1;" ::: "memory")

__device__ __forceinline__ uint32_t swz(int row, int chunk) {
    return (uint32_t)(row * 64 + ((chunk ^ ((row >> 1) & 3)) << 4));
}

__device__ __forceinline__ uint32_t pack_h16x2(float a, float b) {
    __half2 t = __floats2half2_rn(a, b);   // a -> low
    return *(uint32_t*)&t;
}

// ---------------------------------------------------------------------------
// Single-fp16 GEMM (256 threads, 2 CTAs/SM).
// ---------------------------------------------------------------------------
#define BKC 32
#define TILE_B 8192
#define BUF1_B (2 * TILE_B)
#define FG_SMEM (2 * BUF1_B)        // 32 KB

__global__ void __launch_bounds__(256, 2)
f16gemm_kernel(const __half* __restrict__ A, const __half* __restrict__ Bh,
               float* __restrict__ C, int M, int N, int K) {
    extern __shared__ char smem[];
    const uint32_t smem_base = smem_u32(smem);
    const int t = threadIdx.x;
    const int lane = t & 31;
    const int wid = t >> 5;
    const int wm = wid & 1;
    const int wn = wid >> 1;
    const int bm = blockIdx.y * 128;
    const int bn = blockIdx.x * 128;

    const char* srcs[2] = {
        (const char*)(A + (size_t)bm * K),
        (const char*)(Bh + (size_t)bn * K) };

    float acc[4][4][4];
#pragma unroll
    for (int i = 0; i < 4; i++)
#pragma unroll
        for (int j = 0; j < 4; j++)
#pragma unroll
            for (int u = 0; u < 4; u++) acc[i][j][u] = 0.f;

    const int NC = K / BKC;
    const size_t rowb = (size_t)K * 2;

    {
#pragma unroll
        for (int tl = 0; tl < 2; tl++) {
            const char* src = srcs[tl];
            uint32_t dstt = smem_base + tl * TILE_B;
#pragma unroll
            for (int j = 0; j < 2; j++) {
                int idx = t + j * 256;
                int r = idx >> 2, c = idx & 3;
                CP16(dstt + swz(r, c), src + (size_t)r * rowb + c * 16);
            }
        }
        CP_COMMIT();
    }

    for (int ic = 0; ic < NC; ic++) {
        if (ic + 1 < NC) {
            const int k0b = (ic + 1) * BKC * 2;
            uint32_t sbase = smem_base + ((ic + 1) & 1) * BUF1_B;
#pragma unroll
            for (int tl = 0; tl < 2; tl++) {
                const char* src = srcs[tl] + k0b;
                uint32_t dstt = sbase + tl * TILE_B;
#pragma unroll
                for (int j = 0; j < 2; j++) {
                    int idx = t + j * 256;
                    int r = idx >> 2, c = idx & 3;
                    CP16(dstt + swz(r, c), src + (size_t)r * rowb + c * 16);
                }
            }
            CP_COMMIT();
            CP_WAIT1();
        } else {
            CP_WAIT0();
        }
        __syncthreads();

        const uint32_t buf = smem_base + (ic & 1) * BUF1_B;
        const uint32_t a_base = buf;
        const uint32_t b_base = buf + TILE_B;

#pragma unroll
        for (int ks = 0; ks < 2; ks++) {
            uint32_t a_f[4][4];
#pragma unroll
            for (int mt = 0; mt < 4; mt++) {
                int row = wm * 64 + mt * 16 + (lane & 15);
                int chunk = ks * 2 + (lane >> 4);
                ldsm4(a_f[mt], a_base + swz(row, chunk));
            }
            uint32_t b_f[4][2];
#pragma unroll
            for (int np = 0; np < 2; np++) {
                int row = wn * 32 + np * 16 + ((lane >> 4) << 3) + (lane & 7);
                int chunk = ks * 2 + ((lane >> 3) & 1);
                uint32_t r4[4];
                ldsm4(r4, b_base + swz(row, chunk));
                b_f[np * 2][0] = r4[0]; b_f[np * 2][1] = r4[1];
                b_f[np * 2 + 1][0] = r4[2]; b_f[np * 2 + 1][1] = r4[3];
            }
#pragma unroll
            for (int mt = 0; mt < 4; mt++)
#pragma unroll
                for (int nt = 0; nt < 4; nt++)
                    mma16816h(acc[mt][nt], a_f[mt], b_f[nt]);
        }
        __syncthreads();
    }

#pragma unroll
    for (int mt = 0; mt < 4; mt++) {
#pragma unroll
        for (int nt = 0; nt < 4; nt++) {
            int r0 = bm + wm * 64 + mt * 16 + (lane >> 2);
            int col = bn + wn * 32 + nt * 8 + ((lane & 3) << 1);
            float* p0 = C + (size_t)r0 * N + col;
            float* p1 = C + (size_t)(r0 + 8) * N + col;
            p0[0] = acc[mt][nt][0]; p0[1] = acc[mt][nt][1];
            p1[0] = acc[mt][nt][2]; p1[1] = acc[mt][nt][3];
        }
    }
}

// ---------------------------------------------------------------------------
// QKV GEMM; epilogue in two 64-row halves (33 KB smem -> 2 CTAs/SM).
// ---------------------------------------------------------------------------
#define PS_STRIDE 129
#define EPI_B (64 * PS_STRIDE * 4)
#define QKV_SMEM (EPI_B > FG_SMEM ? EPI_B : FG_SMEM)

__global__ void __launch_bounds__(256, 2)
qkvgemm_kernel(const __half* __restrict__ A, const __half* __restrict__ Bh,
               __half* __restrict__ qb, __half* __restrict__ kb,
               __half* __restrict__ vt) {
    extern __shared__ char smem[];
    const uint32_t smem_base = smem_u32(smem);
    const int t = threadIdx.x;
    const int lane = t & 31;
    const int wid = t >> 5;
    const int wm = wid & 1;
    const int wn = wid >> 1;
    const int bm = blockIdx.y * 128;
    const int bn = blockIdx.x * 128;
    const int K = E_;

    const char* srcs[2] = {
        (const char*)(A + (size_t)bm * K),
        (const char*)(Bh + (size_t)bn * K) };

    float acc[4][4][4];
#pragma unroll
    for (int i = 0; i < 4; i++)
#pragma unroll
        for (int j = 0; j < 4; j++)
#pragma unroll
            for (int u = 0; u < 4; u++) acc[i][j][u] = 0.f;

    const int NC = K / BKC;
    const size_t rowb = (size_t)K * 2;

    {
#pragma unroll
        for (int tl = 0; tl < 2; tl++) {
            const char* src = srcs[tl];
            uint32_t dstt = smem_base + tl * TILE_B;
#pragma unroll
            for (int j = 0; j < 2; j++) {
                int idx = t + j * 256;
                int r = idx >> 2, c = idx & 3;
                CP16(dstt + swz(r, c), src + (size_t)r * rowb + c * 16);
            }
        }
        CP_COMMIT();
    }

    for (int ic = 0; ic < NC; ic++) {
        if (ic + 1 < NC) {
            const int k0b = (ic + 1) * BKC * 2;
            uint32_t sbase = smem_base + ((ic + 1) & 1) * BUF1_B;
#pragma unroll
            for (int tl = 0; tl < 2; tl++) {
                const char* src = srcs[tl] + k0b;
                uint32_t dstt = sbase + tl * TILE_B;
#pragma unroll
                for (int j = 0; j < 2; j++) {
                    int idx = t + j * 256;
                    int r = idx >> 2, c = idx & 3;
                    CP16(dstt + swz(r, c), src + (size_t)r * rowb + c * 16);
                }
            }
            CP_COMMIT();
            CP_WAIT1();
        } else {
            CP_WAIT0();
        }
        __syncthreads();

        const uint32_t buf = smem_base + (ic & 1) * BUF1_B;
        const uint32_t a_base = buf;
        const uint32_t b_base = buf + TILE_B;

#pragma unroll
        for (int ks = 0; ks < 2; ks++) {
            uint32_t a_f[4][4];
#pragma unroll
            for (int mt = 0; mt < 4; mt++) {
                int row = wm * 64 + mt * 16 + (lane & 15);
                int chunk = ks * 2 + (lane >> 4);
                ldsm4(a_f[mt], a_base + swz(row, chunk));
            }
            uint32_t b_f[4][2];
#pragma unroll
            for (int np = 0; np < 2; np++) {
                int row = wn * 32 + np * 16 + ((lane >> 4) << 3) + (lane & 7);
                int chunk = ks * 2 + ((lane >> 3) & 1);
                uint32_t r4[4];
                ldsm4(r4, b_base + swz(row, chunk));
                b_f[np * 2][0] = r4[0]; b_f[np * 2][1] = r4[1];
                b_f[np * 2 + 1][0] = r4[2]; b_f[np * 2 + 1][1] = r4[3];
            }
#pragma unroll
            for (int mt = 0; mt < 4; mt++)
#pragma unroll
                for (int nt = 0; nt < 4; nt++)
                    mma16816h(acc[mt][nt], a_f[mt], b_f[nt]);
        }
        __syncthreads();
    }

    // ---- fused epilogue, two 64-row halves ----
    float* ps = (float*)smem;
    const float scale = 0.08838834764831845f;
#pragma unroll
    for (int half = 0; half < 2; half++) {
        __syncthreads();
        if (wm == half) {
#pragma unroll
            for (int mt = 0; mt < 4; mt++) {
#pragma unroll
                for (int nt = 0; nt < 4; nt++) {
                    int r0 = mt * 16 + (lane >> 2);
                    int col = wn * 32 + nt * 8 + ((lane & 3) << 1);
                    ps[r0 * PS_STRIDE + col]       = acc[mt][nt][0];
                    ps[r0 * PS_STRIDE + col + 1]   = acc[mt][nt][1];
                    ps[(r0 + 8) * PS_STRIDE + col]     = acc[mt][nt][2];
                    ps[(r0 + 8) * PS_STRIDE + col + 1] = acc[mt][nt][3];
                }
            }
        }
        __syncthreads();

        const int rowbase = bm + half * 64;
        if (bn < 2048) {
            const int h = bn >> 7;
            for (int idx = t; idx < 64 * 64; idx += 256) {
                int r = idx >> 6, i = idx & 63;
                int tok = rowbase + r;
                int s = tok & (S_ - 1);
                float c  = g_cos[s * 64 + i];
                float sn = g_sin[s * 64 + i];
                float v1 = ps[r * PS_STRIDE + i];
                float v2 = ps[r * PS_STRIDE + 64 + i];
                size_t dst = (size_t)tok * (H_ * D_) + h * 128;
                qb[dst + i]      = __float2half((v1 * c - v2 * sn) * scale);
                qb[dst + 64 + i] = __float2half((v2 * c + v1 * sn) * scale);
            }
        } else if (bn < 2560) {
            const int kvh = (bn - 2048) >> 7;
            for (int idx = t; idx < 64 * 64; idx += 256) {
                int r = idx >> 6, i = idx & 63;
                int tok = rowbase + r;
                int s = tok & (S_ - 1);
                float c  = g_cos[s * 64 + i];
                float sn = g_sin[s * 64 + i];
                float v1 = ps[r * PS_STRIDE + i];
                float v2 = ps[r * PS_STRIDE + 64 + i];
                size_t dst = (size_t)tok * (KV_ * D_) + kvh * 128;
                kb[dst + i]      = __float2half(v1 * c - v2 * sn);
                kb[dst + 64 + i] = __float2half(v2 * c + v1 * sn);
            }
        } else {
            const int kvh = (bn - 2560) >> 7;
            const int b = bm >> 11;
            for (int idx = t; idx < 64 * 128; idx += 256) {
                int d = idx >> 6, rr = idx & 63;
                int tok = rowbase + rr;
                int s = tok & (S_ - 1);
                vt[(size_t)((b * KV_ + kvh) * 128 + d) * S_ + s] =
                    __float2half(ps[rr * PS_STRIDE + d]);
            }
        }
    }
}

// ---------------------------------------------------------------------------
// Conversions
// ---------------------------------------------------------------------------
__global__ void conv_f16_kernel(const float* __restrict__ A,
                                __half* __restrict__ O, int total) {
    int i = blockIdx.x * blockDim.x + threadIdx.x;
    if (i >= total) return;
    O[i] = __float2half(A[i]);
}

__global__ void conv_transpose_all_kernel(const float* __restrict__ Wq,
                                          const float* __restrict__ Wk,
                                          const float* __restrict__ Wv,
                                          const float* __restrict__ Wo,
                                          __half* __restrict__ Wqkvt,
                                          __half* __restrict__ Wot) {
    __shared__ float tile[32][33];
    const int z = blockIdx.z;
    const float* W;
    __half* T;
    int N;
    if (z == 0)      { W = Wq; T = Wqkvt;                       N = 2048; }
    else if (z == 1) { W = Wk; T = Wqkvt + (size_t)2048 * E_;   N = 512; }
    else if (z == 2) { W = Wv; T = Wqkvt + (size_t)2560 * E_;   N = 512; }
    else             { W = Wo; T = Wot;                         N = 2048; }
    int n0 = blockIdx.x * 32;
    if (n0 >= N) return;
    int k0 = blockIdx.y * 32;
    int tx = threadIdx.x & 31, ty = threadIdx.x >> 5;
#pragma unroll
    for (int i = 0; i < 32; i += 8)
        tile[ty + i][tx] = W[(size_t)(k0 + ty + i) * N + n0 + tx];
    __syncthreads();
#pragma unroll
    for (int i = 0; i < 32; i += 8)
        T[(size_t)(n0 + ty + i) * E_ + k0 + tx] = __float2half(tile[tx][ty + i]);
}

// ---------------------------------------------------------------------------
// RoPE tables
// ---------------------------------------------------------------------------
__global__ void build_tables_kernel() {
    int idx = blockIdx.x * blockDim.x + threadIdx.x;
    if (idx >= S_ * 64) return;
    int i = idx & 63;
    int s = idx >> 6;
    double inv = pow(10000.0, -(double)i / 64.0);
    double ang = (double)s * inv;
    g_cos[idx] = (float)cos(ang);
    g_sin[idx] = (float)sin(ang);
}

// ---------------------------------------------------------------------------
// Flash attention: all single fp16 operands (Q, K, P, V), 2 CTAs/SM.
// smem: Q 4x8KB (0..32K); KV buf b at 32K + b*32K (K 4x4KB, V 2x8KB). 96 KB.
// ---------------------------------------------------------------------------
#define ATT_SMEM 98304
#define KV_BUF(buf) (32768 + (buf) * 32768)

__global__ void __launch_bounds__(256, 2)
attn3_kernel(const __half* __restrict__ qb, const __half* __restrict__ kb,
             const __half* __restrict__ vt, __half* __restrict__ oh) {
    extern __shared__ char smem[];
    const uint32_t sb = smem_u32(smem);
    const int qt = (int)gridDim.x - 1 - (int)blockIdx.x;
    const int h = blockIdx.y, b = blockIdx.z;
    const int kvh = h >> 2;
    const int t = threadIdx.x, lane = t & 31, w = t >> 5;
    const int q0 = qt * 128;
    const int kt_end = q0 + 128;

    auto load_kv = [&](int kt, int buf) {
        const uint32_t kvb = sb + KV_BUF(buf);
#pragma unroll
        for (int j = 0; j < 4; j++) {
            int idx = t + j * 256;
            int dc = idx >> 8, rem = idx & 255;
            int r = rem >> 2, c = rem & 3;
            const __half* src =
                kb + (size_t)(b * S_ + kt + r) * (KV_ * D_) + kvh * 128 + dc * 32 + c * 8;
            CP16(kvb + dc * 4096 + swz(r, c), src);
        }
#pragma unroll
        for (int j = 0; j < 4; j++) {
            int idx = t + j * 256;
            int kc = idx >> 9, rem = idx & 511;
            int r = rem >> 2, c = rem & 3;
            const __half* src =
                vt + (size_t)((b * KV_ + kvh) * 128 + r) * S_ + kt + kc * 32 + c * 8;
            CP16(kvb + 16384 + kc * 8192 + swz(r, c), src);
        }
    };

    // prologue: Q (single fp16, 32KB) + KV tile 0
    {
#pragma unroll
        for (int j = 0; j < 8; j++) {
            int idx = t + j * 256;
            int dc = idx >> 9, rem = idx & 511;
            int r = rem >> 2, c = rem & 3;
            const __half* src =
                qb + (size_t)(b * S_ + q0 + r) * (H_ * D_) + h * 128 + dc * 32 + c * 8;
            CP16(sb + dc * 8192 + swz(r, c), src);
        }
        load_kv(0, 0);
        CP_COMMIT();
    }

    float o_acc[16][4];
#pragma unroll
    for (int i = 0; i < 16; i++)
#pragma unroll
        for (int u = 0; u < 4; u++) o_acc[i][u] = 0.f;
    float m0 = -INFINITY, m1 = -INFINITY, l0 = 0.f, l1 = 0.f;

    for (int kt = 0; kt < kt_end; kt += 64) {
        const int ti = kt >> 6;
        if (kt + 64 < kt_end) load_kv(kt + 64, (ti + 1) & 1);
        CP_COMMIT();
        CP_WAIT1();
        __syncthreads();

        const uint32_t kvb = sb + KV_BUF(ti & 1);

        // ---- QK^T: Q single x K single ----
        float sf[8][4];
#pragma unroll
        for (int nt = 0; nt < 8; nt++)
#pragma unroll
            for (int u = 0; u < 4; u++) sf[nt][u] = 0.f;

#pragma unroll
        for (int j = 0; j < 8; j++) {
            int dc = j >> 1, ks = j & 1;
            uint32_t ah[4];
            uint32_t aoff = swz(w * 16 + (lane & 15), ks * 2 + (lane >> 4));
            ldsm4(ah, sb + dc * 8192 + aoff);
            uint32_t bf[8][2];
#pragma unroll
            for (int np = 0; np < 4; np++) {
                uint32_t boff = swz(np * 16 + ((lane >> 4) << 3) + (lane & 7),
                                    ks * 2 + ((lane >> 3) & 1));
                uint32_t r4[4];
                ldsm4(r4, kvb + dc * 4096 + boff);
                bf[np * 2][0] = r4[0]; bf[np * 2][1] = r4[1];
                bf[np * 2 + 1][0] = r4[2]; bf[np * 2 + 1][1] = r4[3];
            }
#pragma unroll
            for (int nt = 0; nt < 8; nt++)
                mma16816h(sf[nt], ah, bf[nt]);
        }

        if (kt + 63 > q0 + w * 16) {
            int row0g = q0 + w * 16 + (lane >> 2);
            int colb = kt + ((lane & 3) << 1);
#pragma unroll
            for (int nt = 0; nt < 8; nt++) {
                int c0 = colb + nt * 8;
                if (c0 > row0g)     sf[nt][0] = -INFINITY;
                if (c0 + 1 > row0g) sf[nt][1] = -INFINITY;
                if (c0 > row0g + 8)     sf[nt][2] = -INFINITY;
                if (c0 + 1 > row0g + 8) sf[nt][3] = -INFINITY;
            }
        }

        float mx0 = -INFINITY, mx1 = -INFINITY;
#pragma unroll
        for (int nt = 0; nt < 8; nt++) {
            mx0 = fmaxf(mx0, fmaxf(sf[nt][0], sf[nt][1]));
            mx1 = fmaxf(mx1, fmaxf(sf[nt][2], sf[nt][3]));
        }
        mx0 = fmaxf(mx0, __shfl_xor_sync(0xffffffffu, mx0, 1));
        mx0 = fmaxf(mx0, __shfl_xor_sync(0xffffffffu, mx0, 2));
        mx1 = fmaxf(mx1, __shfl_xor_sync(0xffffffffu, mx1, 1));
        mx1 = fmaxf(mx1, __shfl_xor_sync(0xffffffffu, mx1, 2));
        float mn0 = fmaxf(m0, mx0), mn1 = fmaxf(m1, mx1);
        float corr0 = __expf(m0 - mn0), corr1 = __expf(m1 - mn1);
        float sum0 = 0.f, sum1 = 0.f;
#pragma unroll
        for (int nt = 0; nt < 8; nt++) {
            float p0 = __expf(sf[nt][0] - mn0); sf[nt][0] = p0; sum0 += p0;
            float p1 = __expf(sf[nt][1] - mn0); sf[nt][1] = p1; sum0 += p1;
            float p2 = __expf(sf[nt][2] - mn1); sf[nt][2] = p2; sum1 += p2;
            float p3 = __expf(sf[nt][3] - mn1); sf[nt][3] = p3; sum1 += p3;
        }
        sum0 += __shfl_xor_sync(0xffffffffu, sum0, 1);
        sum0 += __shfl_xor_sync(0xffffffffu, sum0, 2);
        sum1 += __shfl_xor_sync(0xffffffffu, sum1, 1);
        sum1 += __shfl_xor_sync(0xffffffffu, sum1, 2);
        l0 = l0 * corr0 + sum0;
        l1 = l1 * corr1 + sum1;
        m0 = mn0; m1 = mn1;
#pragma unroll
        for (int i = 0; i < 16; i++) {
            o_acc[i][0] *= corr0; o_acc[i][1] *= corr0;
            o_acc[i][2] *= corr1; o_acc[i][3] *= corr1;
        }

        // ---- PV: single P x single V, two vb sub-passes (register cap) ----
#pragma unroll
        for (int s4 = 0; s4 < 4; s4++) {
            uint32_t ap[4];
#pragma unroll
            for (int half = 0; half < 2; half++) {
                const float* pp = sf[2 * s4 + half];
                ap[half * 2 + 0] = pack_h16x2(pp[0], pp[1]);
                ap[half * 2 + 1] = pack_h16x2(pp[2], pp[3]);
            }
            int kc = s4 >> 1;
            uint32_t chunk = (uint32_t)((s4 & 1) * 2 + ((lane >> 3) & 1));
#pragma unroll
            for (int g = 0; g < 2; g++) {
                uint32_t vb[4][4];
#pragma unroll
                for (int np = 0; np < 4; np++) {
                    int anp = g * 4 + np;
                    uint32_t boff = swz(anp * 16 + ((lane >> 4) << 3) + (lane & 7), chunk);
                    ldsm4(vb[np], kvb + 16384 + kc * 8192 + boff);
                }
#pragma unroll
                for (int np = 0; np < 4; np++) {
                    int anp = g * 4 + np;
                    mma16816h(o_acc[anp * 2], ap, vb[np]);
                    mma16816h(o_acc[anp * 2 + 1], ap, vb[np] + 2);
                }
            }
        }
        __syncthreads();
    }

    float inv0 = 1.f / l0, inv1 = 1.f / l1;
    int row0g = q0 + w * 16 + (lane >> 2);
    size_t base0 = (size_t)(b * S_ + row0g) * (H_ * D_) + h * 128 + ((lane & 3) << 1);
    size_t base1 = base0 + 8 * (size_t)(H_ * D_);
#pragma unroll
    for (int nt = 0; nt < 16; nt++) {
        *(uint32_t*)(oh + base0 + nt * 8) =
            pack_h16x2(o_acc[nt][0] * inv0, o_acc[nt][1] * inv0);
        *(uint32_t*)(oh + base1 + nt * 8) =
            pack_h16x2(o_acc[nt][2] * inv1, o_acc[nt][3] * inv1);
    }
}

// ---------------------------------------------------------------------------
// Launch
// ---------------------------------------------------------------------------
extern "C" void kernel_launch(void* const* d_in, const int* in_sizes, int n_in,
                              void* d_out, int out_size) {
    const float *x, *Wq, *Wk, *Wv, *Wo;
    if (in_sizes[0] == NTOK * E_) {
        x  = (const float*)d_in[0];
        Wq = (const float*)d_in[1];
        Wk = (const float*)d_in[2];
        Wv = (const float*)d_in[3];
        Wo = (const float*)d_in[4];
    } else {
        Wk = (const float*)d_in[0];
        Wo = (const float*)d_in[1];
        Wq = (const float*)d_in[2];
        Wv = (const float*)d_in[3];
        x  = (const float*)d_in[4];
    }
    float* out = (float*)d_out;

    __half *x16, *o16, *qb, *kb, *vt, *Wqkvt16, *Wot16;
    cudaGetSymbolAddress((void**)&x16, g_x16);
    cudaGetSymbolAddress((void**)&o16, g_o16);
    cudaGetSymbolAddress((void**)&qb, g_qb16);
    cudaGetSymbolAddress((void**)&kb, g_kb16);
    cudaGetSymbolAddress((void**)&vt, g_vt16);
    cudaGetSymbolAddress((void**)&Wqkvt16, g_Wqkvt16);
    cudaGetSymbolAddress((void**)&Wot16, g_Wot16);

    cudaFuncSetAttribute(f16gemm_kernel, cudaFuncAttributeMaxDynamicSharedMemorySize, FG_SMEM);
    cudaFuncSetAttribute(qkvgemm_kernel, cudaFuncAttributeMaxDynamicSharedMemorySize, QKV_SMEM);
    cudaFuncSetAttribute(attn3_kernel, cudaFuncAttributeMaxDynamicSharedMemorySize, ATT_SMEM);

    build_tables_kernel<<<(S_ * 64 + 255) / 256, 256>>>();
    conv_f16_kernel<<<(NTOK * E_ + 255) / 256, 256>>>(x, x16, NTOK * E_);
    {
        dim3 g(E_ / 32, E_ / 32, 4);
        conv_transpose_all_kernel<<<g, 256>>>(Wq, Wk, Wv, Wo, Wqkvt16, Wot16);
    }
    {
        dim3 g(NQKV / 128, NTOK / 128);
        qkvgemm_kernel<<<g, 256, QKV_SMEM>>>(x16, Wqkvt16, qb, kb, vt);
    }
    {
        dim3 ga(S_ / 128, H_, B_);
        attn3_kernel<<<ga, 256, ATT_SMEM>>>(qb, kb, vt, o16);
    }
    {
        dim3 go(E_ / 128, NTOK / 128);
        f16gemm_kernel<<<go, 256, FG_SMEM>>>(o16, Wot16, out, NTOK, E_, E_);
    }
}